// round 13
// baseline (speedup 1.0000x reference)
#include <cuda_runtime.h>
#include <cuda_fp16.h>
#include <math.h>
#include <stdint.h>

#define N_NODES 100000
#define N_PAD   100096   // multiple of 128
#define N_EDGES 1600000
#define N_TOT   1700000
#define N_GRAPHS 256
#define BN_EPS 1e-5f

#define SCAN_BLOCKS 512
#define SCAN_CHUNK  ((N_NODES + SCAN_BLOCKS - 1) / SCAN_BLOCKS)   // 196

// ---------------- scratch (device globals; no runtime allocation) -------------
__device__ int    g_idx64;
__device__ int    g_deg[N_NODES];
__device__ float  g_dinv[N_NODES];
__device__ int    g_off[N_NODES + 1];
__device__ int    g_blocksum[SCAN_BLOCKS];
__device__ int    g_cursor[N_NODES];
__device__ int    g_srcarr[N_TOT];
__device__ float  g_normarr[N_TOT];
__device__ __half g_hA[(size_t)N_PAD * 200];
__device__ __half g_hB[(size_t)N_PAD * 200];
__device__ float  g_stats[512];
__device__ float  g_scale[256];
__device__ float  g_shift[256];
__device__ int    g_gstart[N_GRAPHS + 1];
// pre-converted fp16 weights, transposed [n][k], per-chunk stride SA=KPAD+8
__device__ __align__(16) __half g_Wt[58880];

__device__ __forceinline__ int idx_at(const void* p, long i, int is64) {
    if (is64) return (int)((const long long*)p)[i];
    return ((const int*)p)[i];
}
// load two consecutive indices at position i (i even not required; arrays 8B aligned)
__device__ __forceinline__ int2 idx2_at(const void* p, long i, int is64) {
    if (is64) {
        longlong2 v = __ldg((const longlong2*)((const long long*)p + i));
        return make_int2((int)v.x, (int)v.y);
    }
    return __ldg((const int2*)((const int*)p + i));
}

// ---------------- init ----------------
__global__ void __launch_bounds__(256) k_init(const int* __restrict__ ei32) {
    int n = blockIdx.x * blockDim.x + threadIdx.x;
    if (n < N_NODES) g_deg[n] = 1;
    if (n < 512) g_stats[n] = 0.0f;
    if (n == 0) {
        int any = 0;
        for (int k = 0; k < 64; k++)
            if (ei32[2 * k + 1] != 0) { any = 1; break; }
        g_idx64 = !any;
    }
}

// 2 edges per thread
__global__ void __launch_bounds__(256) k_deg_edges(const void* __restrict__ ei) {
    int t = blockIdx.x * blockDim.x + threadIdx.x;
    long e = (long)t * 2;
    if (e + 1 < N_EDGES) {
        int is64 = g_idx64;
        int2 d = idx2_at(ei, (long)N_EDGES + e, is64);
        if ((unsigned)d.x < N_NODES) atomicAdd(&g_deg[d.x], 1);
        if ((unsigned)d.y < N_NODES) atomicAdd(&g_deg[d.y], 1);
    } else if (e < N_EDGES) {
        int is64 = g_idx64;
        int d = idx_at(ei, (long)N_EDGES + e, is64);
        if ((unsigned)d < N_NODES) atomicAdd(&g_deg[d], 1);
    }
}

__global__ void __launch_bounds__(256) k_scan1() {
    __shared__ int sh[256];
    int b = blockIdx.x, t = threadIdx.x;
    int idx = b * SCAN_CHUNK + t;
    int v = 0;
    if (t < SCAN_CHUNK && idx < N_NODES) {
        v = g_deg[idx];
        g_dinv[idx] = rsqrtf((float)v);
    }
    sh[t] = v;
    __syncthreads();
    for (int o = 1; o < 256; o <<= 1) {
        int a = (t >= o) ? sh[t - o] : 0;
        __syncthreads();
        sh[t] += a;
        __syncthreads();
    }
    if (t < SCAN_CHUNK && idx < N_NODES) g_off[idx] = sh[t] - v;
    if (t == 255) g_blocksum[b] = sh[255];
}

__global__ void __launch_bounds__(256) k_scan2() {
    __shared__ int sh[256];
    int t = threadIdx.x;
    int a0 = g_blocksum[2 * t];
    int a1 = g_blocksum[2 * t + 1];
    sh[t] = a0 + a1;
    __syncthreads();
    for (int o = 1; o < 256; o <<= 1) {
        int v = (t >= o) ? sh[t - o] : 0;
        __syncthreads();
        sh[t] += v;
        __syncthreads();
    }
    int pre = (t == 0) ? 0 : sh[t - 1];
    g_blocksum[2 * t] = pre;
    g_blocksum[2 * t + 1] = pre + a0;
    if (t == 255) g_off[N_NODES] = sh[255];
}

// scan fixup + self-loop entry + cursor + graph-boundary scatter (batch sorted)
__global__ void __launch_bounds__(256) k_scan3(const void* __restrict__ batch) {
    int n = blockIdx.x * blockDim.x + threadIdx.x;
    if (n < N_NODES) {
        int o = g_off[n] + g_blocksum[n / SCAN_CHUNK];
        g_off[n] = o;
        g_srcarr[o] = n;
        float di = g_dinv[n];
        g_normarr[o] = di * di;
        g_cursor[n] = o + 1;
        int is64 = g_idx64;
        int b1 = idx_at(batch, n, is64);
        if (b1 >= 0 && b1 < N_GRAPHS) {
            int b0 = (n == 0) ? -1 : idx_at(batch, n - 1, is64);
            for (int g = b0 + 1; g <= b1; g++) g_gstart[g] = n;
            if (n == N_NODES - 1)
                for (int g = b1 + 1; g <= N_GRAPHS; g++) g_gstart[g] = N_NODES;
        }
    }
}

// 2 edges per thread
__global__ void __launch_bounds__(256) k_fill(const void* __restrict__ ei) {
    int t = blockIdx.x * blockDim.x + threadIdx.x;
    long e = (long)t * 2;
    int is64 = g_idx64;
    if (e + 1 < N_EDGES) {
        int2 s = idx2_at(ei, e, is64);
        int2 d = idx2_at(ei, (long)N_EDGES + e, is64);
        if ((unsigned)s.x < N_NODES && (unsigned)d.x < N_NODES) {
            int pos = atomicAdd(&g_cursor[d.x], 1);
            if ((unsigned)pos < N_TOT) {
                g_srcarr[pos] = s.x;
                g_normarr[pos] = g_dinv[s.x] * g_dinv[d.x];
            }
        }
        if ((unsigned)s.y < N_NODES && (unsigned)d.y < N_NODES) {
            int pos = atomicAdd(&g_cursor[d.y], 1);
            if ((unsigned)pos < N_TOT) {
                g_srcarr[pos] = s.y;
                g_normarr[pos] = g_dinv[s.y] * g_dinv[d.y];
            }
        }
    } else if (e < N_EDGES) {
        int s = idx_at(ei, e, is64);
        int d = idx_at(ei, (long)N_EDGES + e, is64);
        if ((unsigned)s < N_NODES && (unsigned)d < N_NODES) {
            int pos = atomicAdd(&g_cursor[d], 1);
            if ((unsigned)pos < N_TOT) {
                g_srcarr[pos] = s;
                g_normarr[pos] = g_dinv[s] * g_dinv[d];
            }
        }
    }
}

// ---------------- W pre-conversion: fp16, transposed, padded -----------------
template <int FI, int KPAD, int FO>
__global__ void __launch_bounds__(256) k_wprep(const float* __restrict__ W, int off) {
    const int SA = KPAD + 8;
    int jc = blockIdx.x;
    int j0 = jc * 64;
    __half* dst = g_Wt + off + (size_t)jc * 64 * SA;
    for (int idx = threadIdx.x; idx < 64 * SA; idx += 256) {
        int nn = idx / SA, k = idx - nn * SA;
        float v = (k < FI && (j0 + nn) < FO) ? __ldg(&W[k * FO + j0 + nn]) : 0.f;
        dst[idx] = __float2half_rn(v);
    }
}

// ---------------- stats over external x (layer 0 only) ----------------
__global__ void __launch_bounds__(256) k_stats_x(const float* __restrict__ x, int FI) {
    int f = threadIdx.x;
    float s = 0.f, sq = 0.f;
    if (f < FI) {
        for (int n = blockIdx.y * blockDim.y + threadIdx.y; n < N_NODES;
             n += gridDim.y * blockDim.y) {
            float v = x[(size_t)n * FI + f];
            s += v;
            sq += v * v;
        }
    }
    __shared__ float shs[8][32];
    __shared__ float shq[8][32];
    shs[threadIdx.y][threadIdx.x] = s;
    shq[threadIdx.y][threadIdx.x] = sq;
    __syncthreads();
    if (threadIdx.y == 0 && f < FI) {
        float ts = 0.f, tq = 0.f;
        #pragma unroll
        for (int y = 0; y < 8; y++) { ts += shs[y][threadIdx.x]; tq += shq[y][threadIdx.x]; }
        atomicAdd(&g_stats[f], ts);
        atomicAdd(&g_stats[256 + f], tq);
    }
}

__global__ void __launch_bounds__(256) k_finalize(const float* __restrict__ gam,
                                                  const float* __restrict__ bet, int FI) {
    int k = threadIdx.x;
    if (k < FI) {
        float m = g_stats[k] * (1.0f / N_NODES);
        float v = g_stats[256 + k] * (1.0f / N_NODES) - m * m;
        float a = gam[k] * rsqrtf(v + BN_EPS);
        g_scale[k] = a;
        g_shift[k] = bet[k] - m * a;
    } else {
        g_scale[k] = 0.f;
        g_shift[k] = 0.f;
    }
    g_stats[k] = 0.f;
    g_stats[256 + k] = 0.f;
}

// ---------------- layer-1 gather (external fp32 x, FI=7 -> padded 8) ---------
__global__ void __launch_bounds__(256) k_gather1(const float* __restrict__ x) {
    const int FI = 7, FIP = 8, LPN = 8;
    int gid = blockIdx.x * blockDim.x + threadIdx.x;
    int node = gid / LPN;
    int lane = gid % LPN;
    if (node >= N_NODES) return;
    int beg = g_off[node], end = g_off[node + 1];
    float acc = 0.f, sumw = 0.f;
    int e = beg;
    for (; e + 3 < end; e += 4) {
        int s0 = __ldg(&g_srcarr[e]);
        int s1 = __ldg(&g_srcarr[e + 1]);
        int s2 = __ldg(&g_srcarr[e + 2]);
        int s3 = __ldg(&g_srcarr[e + 3]);
        float w0 = __ldg(&g_normarr[e]);
        float w1 = __ldg(&g_normarr[e + 1]);
        float w2 = __ldg(&g_normarr[e + 2]);
        float w3 = __ldg(&g_normarr[e + 3]);
        sumw += (w0 + w1) + (w2 + w3);
        if (lane < FI) {
            float v0 = __ldg(&x[(size_t)s0 * FI + lane]);
            float v1 = __ldg(&x[(size_t)s1 * FI + lane]);
            float v2 = __ldg(&x[(size_t)s2 * FI + lane]);
            float v3 = __ldg(&x[(size_t)s3 * FI + lane]);
            acc += (w0 * v0 + w1 * v1) + (w2 * v2 + w3 * v3);
        }
    }
    for (; e < end; e++) {
        int s = __ldg(&g_srcarr[e]);
        float wn = __ldg(&g_normarr[e]);
        sumw += wn;
        if (lane < FI) acc += wn * __ldg(&x[(size_t)s * FI + lane]);
    }
    float r = g_scale[lane] * acc + g_shift[lane] * sumw;
    g_hA[(size_t)node * FIP + lane] = __float2half_rn(r);
}

// ---------------- fp16 gather: LPN lanes/node, 8 halves (uint4) per lane -----
__device__ __forceinline__ void acc_u4(float* acc, float wn, uint4 v) {
    float2 f0 = __half22float2(*(__half2*)&v.x);
    float2 f1 = __half22float2(*(__half2*)&v.y);
    float2 f2 = __half22float2(*(__half2*)&v.z);
    float2 f3 = __half22float2(*(__half2*)&v.w);
    acc[0] += wn * f0.x; acc[1] += wn * f0.y;
    acc[2] += wn * f1.x; acc[3] += wn * f1.y;
    acc[4] += wn * f2.x; acc[5] += wn * f2.y;
    acc[6] += wn * f3.x; acc[7] += wn * f3.y;
}

template <int LPN, bool SRC_B>
__global__ void __launch_bounds__(256) k_gatherh() {
    int gid = blockIdx.x * blockDim.x + threadIdx.x;
    int node = gid / LPN;
    int lane = gid - node * LPN;
    if (node >= N_NODES) return;
    int beg = g_off[node], end = g_off[node + 1];
    const uint4* in8 = (const uint4*)(SRC_B ? g_hB : g_hA);
    uint4* out8 = (uint4*)(SRC_B ? g_hA : g_hB);
    float acc[8];
    #pragma unroll
    for (int q = 0; q < 8; q++) acc[q] = 0.f;
    float sumw = 0.f;
    int e = beg;
    for (; e + 3 < end; e += 4) {
        int s0 = __ldg(&g_srcarr[e]);
        int s1 = __ldg(&g_srcarr[e + 1]);
        int s2 = __ldg(&g_srcarr[e + 2]);
        int s3 = __ldg(&g_srcarr[e + 3]);
        float w0 = __ldg(&g_normarr[e]);
        float w1 = __ldg(&g_normarr[e + 1]);
        float w2 = __ldg(&g_normarr[e + 2]);
        float w3 = __ldg(&g_normarr[e + 3]);
        uint4 v0 = __ldg(&in8[(size_t)s0 * LPN + lane]);
        uint4 v1 = __ldg(&in8[(size_t)s1 * LPN + lane]);
        uint4 v2 = __ldg(&in8[(size_t)s2 * LPN + lane]);
        uint4 v3 = __ldg(&in8[(size_t)s3 * LPN + lane]);
        sumw += (w0 + w1) + (w2 + w3);
        acc_u4(acc, w0, v0);
        acc_u4(acc, w1, v1);
        acc_u4(acc, w2, v2);
        acc_u4(acc, w3, v3);
    }
    for (; e < end; e++) {
        int s = __ldg(&g_srcarr[e]);
        float wn = __ldg(&g_normarr[e]);
        sumw += wn;
        uint4 v = __ldg(&in8[(size_t)s * LPN + lane]);
        acc_u4(acc, wn, v);
    }
    int c = lane * 8;
    __half2 h[4];
    #pragma unroll
    for (int q = 0; q < 4; q++) {
        float v0 = g_scale[c + 2 * q]     * acc[2 * q]     + g_shift[c + 2 * q]     * sumw;
        float v1 = g_scale[c + 2 * q + 1] * acc[2 * q + 1] + g_shift[c + 2 * q + 1] * sumw;
        h[q] = __floats2half2_rn(v0, v1);
    }
    uint4 o;
    o.x = *(uint32_t*)&h[0]; o.y = *(uint32_t*)&h[1];
    o.z = *(uint32_t*)&h[2]; o.w = *(uint32_t*)&h[3];
    out8[(size_t)node * LPN + lane] = o;
}

// ---------------- fp16 mma GEMM: out = relu(in @ W + bias) -------------------
template <int FIP, int KPAD, int FO, int FOP, int NJ, bool STATS, bool SRC_A>
__global__ void __launch_bounds__(256) k_gemm_h(int woff, const float* __restrict__ bias) {
    const int SA = KPAD + 8;
    __shared__ __align__(16) __half Asm[64 * SA];
    __shared__ __align__(16) __half Wsm[64 * SA];
    __shared__ float  sred[64];
    __shared__ float  sqred[64];

    int tid = threadIdx.x;
    int wid = tid >> 5, lane = tid & 31;
    int grp = lane >> 2, tg = lane & 3;
    int mwarp = (wid & 1) * 32;
    int nwarp = (wid >> 1) * 16;
    int n0 = blockIdx.x * 64;
    const __half* inb = SRC_A ? g_hA : g_hB;
    __half* outb = SRC_A ? g_hB : g_hA;

    // stage A once
    {
        const int VR = KPAD / 8;
        const uint4* src = (const uint4*)inb;
        for (int idx = tid; idx < 64 * VR; idx += 256) {
            int r = idx / VR, q = idx - r * VR;
            uint4 v = make_uint4(0, 0, 0, 0);
            if (n0 + r < N_NODES && q < FIP / 8)
                v = __ldg(&src[(size_t)(n0 + r) * (FIP / 8) + q]);
            *(uint4*)&Asm[r * SA + q * 8] = v;
        }
    }

    for (int jc = 0; jc < NJ; jc++) {
        int j0 = jc * 64;
        __syncthreads();
        {
            const uint4* wsrc = (const uint4*)(g_Wt + woff + (size_t)jc * 64 * SA);
            uint4* wdst = (uint4*)Wsm;
            #pragma unroll 4
            for (int i = tid; i < 64 * SA / 8; i += 256) wdst[i] = __ldg(&wsrc[i]);
        }
        if (STATS && tid < 64) { sred[tid] = 0.f; sqred[tid] = 0.f; }
        __syncthreads();

        float c[2][2][4];
        #pragma unroll
        for (int mi = 0; mi < 2; mi++)
            #pragma unroll
            for (int ni = 0; ni < 2; ni++)
                #pragma unroll
                for (int q = 0; q < 4; q++) c[mi][ni][q] = 0.f;

        const int NS = KPAD / 16;
        #pragma unroll
        for (int ks = 0; ks < NS; ks++) {
            int kb = ks * 16;
            uint32_t a[2][4];
            #pragma unroll
            for (int mi = 0; mi < 2; mi++) {
                int row = mwarp + mi * 16 + grp;
                const __half* ap = &Asm[row * SA + kb + 2 * tg];
                a[mi][0] = *(const uint32_t*)ap;
                a[mi][1] = *(const uint32_t*)(ap + 8 * SA);
                a[mi][2] = *(const uint32_t*)(ap + 8);
                a[mi][3] = *(const uint32_t*)(ap + 8 * SA + 8);
            }
            uint32_t b[2][2];
            #pragma unroll
            for (int ni = 0; ni < 2; ni++) {
                int nn = nwarp + ni * 8 + grp;
                const __half* bp = &Wsm[nn * SA + kb + 2 * tg];
                b[ni][0] = *(const uint32_t*)bp;
                b[ni][1] = *(const uint32_t*)(bp + 8);
            }
            #pragma unroll
            for (int mi = 0; mi < 2; mi++)
                #pragma unroll
                for (int ni = 0; ni < 2; ni++) {
                    asm volatile(
                        "mma.sync.aligned.m16n8k16.row.col.f32.f16.f16.f32 "
                        "{%0,%1,%2,%3}, {%4,%5,%6,%7}, {%8,%9}, {%0,%1,%2,%3};"
                        : "+f"(c[mi][ni][0]), "+f"(c[mi][ni][1]),
                          "+f"(c[mi][ni][2]), "+f"(c[mi][ni][3])
                        : "r"(a[mi][0]), "r"(a[mi][1]), "r"(a[mi][2]), "r"(a[mi][3]),
                          "r"(b[ni][0]), "r"(b[ni][1]));
                }
        }

        #pragma unroll
        for (int mi = 0; mi < 2; mi++) {
            int r0 = n0 + mwarp + mi * 16 + grp;
            int r1 = r0 + 8;
            #pragma unroll
            for (int ni = 0; ni < 2; ni++) {
                int jb = j0 + nwarp + ni * 8 + 2 * tg;
                if (jb >= FO) continue;
                float bj0 = __ldg(&bias[jb]);
                float bj1 = (jb + 1 < FO) ? __ldg(&bias[jb + 1]) : 0.f;
                float v00 = c[mi][ni][0] + bj0; v00 = v00 > 0.f ? v00 : 0.f;
                float v01 = c[mi][ni][1] + bj1; v01 = v01 > 0.f ? v01 : 0.f;
                float v10 = c[mi][ni][2] + bj0; v10 = v10 > 0.f ? v10 : 0.f;
                float v11 = c[mi][ni][3] + bj1; v11 = v11 > 0.f ? v11 : 0.f;
                if (jb + 1 >= FO) { v01 = 0.f; v11 = 0.f; }
                bool ok0 = (r0 < N_NODES), ok1 = (r1 < N_NODES);
                __half2 p0 = __floats2half2_rn(v00, v01);
                __half2 p1 = __floats2half2_rn(v10, v11);
                if (ok0) *(uint32_t*)&outb[(size_t)r0 * FOP + jb] = *(uint32_t*)&p0;
                if (ok1) *(uint32_t*)&outb[(size_t)r1 * FOP + jb] = *(uint32_t*)&p1;
                if (STATS) {
                    float s0 = (ok0 ? v00 : 0.f) + (ok1 ? v10 : 0.f);
                    float q0 = (ok0 ? v00 * v00 : 0.f) + (ok1 ? v10 * v10 : 0.f);
                    float s1 = (ok0 ? v01 : 0.f) + (ok1 ? v11 : 0.f);
                    float q1 = (ok0 ? v01 * v01 : 0.f) + (ok1 ? v11 * v11 : 0.f);
                    int cb = nwarp + ni * 8 + 2 * tg;
                    atomicAdd(&sred[cb], s0);
                    atomicAdd(&sqred[cb], q0);
                    atomicAdd(&sred[cb + 1], s1);
                    atomicAdd(&sqred[cb + 1], q1);
                }
            }
        }
        if (STATS) {
            __syncthreads();
            if (tid < 64) {
                int j = j0 + tid;
                if (j < FO) {
                    atomicAdd(&g_stats[j], sred[tid]);
                    atomicAdd(&g_stats[256 + j], sqred[tid]);
                }
            }
        }
    }
}

// ---------------- fused mean-pool + MLP head (hB fp16, stride 200) ----------
__global__ void __launch_bounds__(256) k_poolmlp(const float* __restrict__ Wl1,
                                                 const float* __restrict__ bl1,
                                                 const float* __restrict__ Wl2,
                                                 const float* __restrict__ bl2,
                                                 float* __restrict__ out) {
    const int FO = 199, FOP = 200;
    __shared__ float pooled[FO];
    __shared__ float t1[49];
    int g = blockIdx.x;
    int s = g_gstart[g], e = g_gstart[g + 1];
    int f = threadIdx.x;
    if (f < FO) {
        float a0 = 0.f, a1 = 0.f, a2 = 0.f, a3 = 0.f;
        int n = s;
        for (; n + 3 < e; n += 4) {
            a0 += __half2float(__ldg(&g_hB[(size_t)n * FOP + f]));
            a1 += __half2float(__ldg(&g_hB[(size_t)(n + 1) * FOP + f]));
            a2 += __half2float(__ldg(&g_hB[(size_t)(n + 2) * FOP + f]));
            a3 += __half2float(__ldg(&g_hB[(size_t)(n + 3) * FOP + f]));
        }
        for (; n < e; n++) a0 += __half2float(__ldg(&g_hB[(size_t)n * FOP + f]));
        float acc = (a0 + a1) + (a2 + a3);
        int cnt = e - s;
        pooled[f] = acc / (float)(cnt > 0 ? cnt : 1);
    }
    __syncthreads();
    if (f < 49) {
        float a = bl1[f];
        for (int k = 0; k < FO; k++) a += pooled[k] * Wl1[k * 49 + f];
        t1[f] = a;
    }
    __syncthreads();
    if (f < 2) {
        float a = bl2[f];
        for (int k = 0; k < 49; k++) a += t1[k] * Wl2[k * 2 + f];
        out[g * 2 + f] = a;
    }
}

// ---------------- launch ----------------
extern "C" void kernel_launch(void* const* d_in, const int* in_sizes, int n_in,
                              void* d_out, int out_size) {
    const float* x     = (const float*)d_in[0];
    const void*  ei    = d_in[1];
    const void*  batch = d_in[2];
    const float* bn0g = (const float*)d_in[3];
    const float* bn0b = (const float*)d_in[4];
    const float* bn1g = (const float*)d_in[5];
    const float* bn1b = (const float*)d_in[6];
    const float* bn2g = (const float*)d_in[7];
    const float* bn2b = (const float*)d_in[8];
    const float* W1  = (const float*)d_in[9];
    const float* b1  = (const float*)d_in[10];
    const float* W2  = (const float*)d_in[11];
    const float* b2  = (const float*)d_in[12];
    const float* W3  = (const float*)d_in[13];
    const float* b3  = (const float*)d_in[14];
    const float* Wl1 = (const float*)d_in[15];
    const float* bl1 = (const float*)d_in[16];
    const float* Wl2 = (const float*)d_in[17];
    const float* bl2 = (const float*)d_in[18];
    float* out = (float*)d_out;

    const int NB_N  = (N_NODES + 255) / 256;
    const int NB_E2 = ((N_EDGES / 2) + 255) / 256;

    // graph preprocessing
    k_init<<<NB_N, 256>>>((const int*)ei);
    k_deg_edges<<<NB_E2, 256>>>(ei);
    k_scan1<<<SCAN_BLOCKS, 256>>>();
    k_scan2<<<1, 256>>>();
    k_scan3<<<NB_N, 256>>>(batch);
    k_fill<<<NB_E2, 256>>>(ei);

    // pre-convert weights
    k_wprep<7, 16, 71><<<2, 256>>>(W1, 0);
    k_wprep<71, 80, 135><<<3, 256>>>(W2, 3072);
    k_wprep<135, 144, 199><<<4, 256>>>(W3, 19968);

    dim3 sblk(32, 8);
    const int NB_G8  = ((N_NODES * 8)  + 255) / 256;
    const int NB_G9  = ((N_NODES * 9)  + 255) / 256;
    const int NB_G17 = ((N_NODES * 17) + 255) / 256;
    const int GX64 = N_PAD / 64;

    // ---- layer 1
    k_stats_x<<<dim3(1, 64), sblk>>>(x, 7);
    k_finalize<<<1, 256>>>(bn0g, bn0b, 7);
    k_gather1<<<NB_G8, 256>>>(x);
    k_gemm_h<8, 16, 71, 72, 2, true, true><<<GX64, 256>>>(0, b1);

    // ---- layer 2
    k_finalize<<<1, 256>>>(bn1g, bn1b, 71);
    k_gatherh<9, true><<<NB_G9, 256>>>();
    k_gemm_h<72, 80, 135, 136, 3, true, true><<<GX64, 256>>>(3072, b2);

    // ---- layer 3
    k_finalize<<<1, 256>>>(bn2g, bn2b, 135);
    k_gatherh<17, true><<<NB_G17, 256>>>();
    k_gemm_h<136, 144, 199, 200, 4, false, true><<<GX64, 256>>>(19968, b3);

    // ---- pool + head
    k_poolmlp<<<N_GRAPHS, 256>>>(Wl1, bl1, Wl2, bl2, out);
}

// round 14
// speedup vs baseline: 1.0756x; 1.0756x over previous
#include <cuda_runtime.h>
#include <cuda_fp16.h>
#include <math.h>
#include <stdint.h>

#define N_NODES 100000
#define N_PAD   100096   // multiple of 128
#define N_EDGES 1600000
#define N_TOT   1700000
#define N_GRAPHS 256
#define BN_EPS 1e-5f

#define SCAN_BLOCKS 512
#define SCAN_CHUNK  ((N_NODES + SCAN_BLOCKS - 1) / SCAN_BLOCKS)   // 196

// ---------------- scratch (device globals; no runtime allocation) -------------
__device__ int    g_idx64;
__device__ int    g_deg[N_NODES];
__device__ float  g_dinv[N_NODES];
__device__ int    g_off[N_NODES + 1];
__device__ int    g_blocksum[SCAN_BLOCKS];
__device__ int    g_cursor[N_NODES];
__device__ int    g_srcarr[N_TOT];
__device__ float  g_normarr[N_TOT];
__device__ __half g_hA[(size_t)N_PAD * 200];
__device__ __half g_hB[(size_t)N_PAD * 200];
__device__ float  g_stats[3 * 512];   // per-layer: [soff + 0..255]=sum, [soff+256..511]=sumsq
__device__ int    g_gstart[N_GRAPHS + 1];
// pre-converted fp16 weights, transposed [n][k], per-chunk stride SA=KPAD+8
__device__ __align__(16) __half g_Wt[58880];

__device__ __forceinline__ int idx_at(const void* p, long i, int is64) {
    if (is64) return (int)((const long long*)p)[i];
    return ((const int*)p)[i];
}

// ---------------- init ----------------
__global__ void __launch_bounds__(256) k_init(const int* __restrict__ ei32) {
    int n = blockIdx.x * blockDim.x + threadIdx.x;
    if (n < N_NODES) g_deg[n] = 1;
    if (n < 3 * 512) g_stats[n] = 0.0f;
    if (n == 0) {
        int any = 0;
        for (int k = 0; k < 64; k++)
            if (ei32[2 * k + 1] != 0) { any = 1; break; }
        g_idx64 = !any;
    }
}

__global__ void __launch_bounds__(256) k_deg_edges(const void* __restrict__ ei) {
    int e = blockIdx.x * blockDim.x + threadIdx.x;
    if (e < N_EDGES) {
        int is64 = g_idx64;
        int d = idx_at(ei, (long)N_EDGES + e, is64);
        if ((unsigned)d < N_NODES) atomicAdd(&g_deg[d], 1);
    }
}

__global__ void __launch_bounds__(256) k_scan1() {
    __shared__ int sh[256];
    int b = blockIdx.x, t = threadIdx.x;
    int idx = b * SCAN_CHUNK + t;
    int v = 0;
    if (t < SCAN_CHUNK && idx < N_NODES) {
        v = g_deg[idx];
        g_dinv[idx] = rsqrtf((float)v);
    }
    sh[t] = v;
    __syncthreads();
    for (int o = 1; o < 256; o <<= 1) {
        int a = (t >= o) ? sh[t - o] : 0;
        __syncthreads();
        sh[t] += a;
        __syncthreads();
    }
    if (t < SCAN_CHUNK && idx < N_NODES) g_off[idx] = sh[t] - v;
    if (t == 255) g_blocksum[b] = sh[255];
}

__global__ void __launch_bounds__(256) k_scan2() {
    __shared__ int sh[256];
    int t = threadIdx.x;
    int a0 = g_blocksum[2 * t];
    int a1 = g_blocksum[2 * t + 1];
    sh[t] = a0 + a1;
    __syncthreads();
    for (int o = 1; o < 256; o <<= 1) {
        int v = (t >= o) ? sh[t - o] : 0;
        __syncthreads();
        sh[t] += v;
        __syncthreads();
    }
    int pre = (t == 0) ? 0 : sh[t - 1];
    g_blocksum[2 * t] = pre;
    g_blocksum[2 * t + 1] = pre + a0;
    if (t == 255) g_off[N_NODES] = sh[255];
}

// scan fixup + self-loop entry + cursor + graph-boundary scatter (batch sorted)
__global__ void __launch_bounds__(256) k_scan3(const void* __restrict__ batch) {
    int n = blockIdx.x * blockDim.x + threadIdx.x;
    if (n < N_NODES) {
        int o = g_off[n] + g_blocksum[n / SCAN_CHUNK];
        g_off[n] = o;
        g_srcarr[o] = n;
        float di = g_dinv[n];
        g_normarr[o] = di * di;
        g_cursor[n] = o + 1;
        int is64 = g_idx64;
        int b1 = idx_at(batch, n, is64);
        if (b1 >= 0 && b1 < N_GRAPHS) {
            int b0 = (n == 0) ? -1 : idx_at(batch, n - 1, is64);
            for (int g = b0 + 1; g <= b1; g++) g_gstart[g] = n;
            if (n == N_NODES - 1)
                for (int g = b1 + 1; g <= N_GRAPHS; g++) g_gstart[g] = N_NODES;
        }
    }
}

__global__ void __launch_bounds__(256) k_fill(const void* __restrict__ ei) {
    int e = blockIdx.x * blockDim.x + threadIdx.x;
    if (e < N_EDGES) {
        int is64 = g_idx64;
        int s = idx_at(ei, e, is64);
        int d = idx_at(ei, (long)N_EDGES + e, is64);
        if ((unsigned)s < N_NODES && (unsigned)d < N_NODES) {
            int pos = atomicAdd(&g_cursor[d], 1);
            if ((unsigned)pos < N_TOT) {
                g_srcarr[pos] = s;
                g_normarr[pos] = g_dinv[s] * g_dinv[d];
            }
        }
    }
}

// ---------------- W pre-conversion (all 3 layers in one launch, 9 blocks) ----
__global__ void __launch_bounds__(256) k_wprep_all(const float* __restrict__ W1,
                                                   const float* __restrict__ W2,
                                                   const float* __restrict__ W3) {
    int b = blockIdx.x;
    const float* W; int FI, KPAD, FO, off, jc;
    if (b < 2)      { W = W1; FI = 7;   KPAD = 16;  FO = 71;  off = 0;     jc = b; }
    else if (b < 5) { W = W2; FI = 71;  KPAD = 80;  FO = 135; off = 3072;  jc = b - 2; }
    else            { W = W3; FI = 135; KPAD = 144; FO = 199; off = 19968; jc = b - 5; }
    int SA = KPAD + 8;
    int j0 = jc * 64;
    __half* dst = g_Wt + off + jc * 64 * SA;
    for (int idx = threadIdx.x; idx < 64 * SA; idx += 256) {
        int nn = idx / SA, k = idx - nn * SA;
        float v = (k < FI && (j0 + nn) < FO) ? __ldg(&W[k * FO + j0 + nn]) : 0.f;
        dst[idx] = __float2half_rn(v);
    }
}

// ---------------- stats over external x (layer 0 only, into buffer 0) --------
__global__ void __launch_bounds__(256) k_stats_x(const float* __restrict__ x, int FI) {
    int f = threadIdx.x;
    float s = 0.f, sq = 0.f;
    if (f < FI) {
        for (int n = blockIdx.y * blockDim.y + threadIdx.y; n < N_NODES;
             n += gridDim.y * blockDim.y) {
            float v = x[(size_t)n * FI + f];
            s += v;
            sq += v * v;
        }
    }
    __shared__ float shs[8][32];
    __shared__ float shq[8][32];
    shs[threadIdx.y][threadIdx.x] = s;
    shq[threadIdx.y][threadIdx.x] = sq;
    __syncthreads();
    if (threadIdx.y == 0 && f < FI) {
        float ts = 0.f, tq = 0.f;
        #pragma unroll
        for (int y = 0; y < 8; y++) { ts += shs[y][threadIdx.x]; tq += shq[y][threadIdx.x]; }
        atomicAdd(&g_stats[f], ts);
        atomicAdd(&g_stats[256 + f], tq);
    }
}

// per-block BN finalize into smem (replaces the k_finalize launches)
__device__ __forceinline__ void bn_smem(float* s_scale, float* s_shift, int FI, int soff,
                                        const float* gam, const float* bet) {
    int t = threadIdx.x;
    float sc = 0.f, sh = 0.f;
    if (t < FI) {
        float m = g_stats[soff + t] * (1.0f / N_NODES);
        float v = g_stats[soff + 256 + t] * (1.0f / N_NODES) - m * m;
        float a = __ldg(&gam[t]) * rsqrtf(v + BN_EPS);
        sc = a;
        sh = __ldg(&bet[t]) - m * a;
    }
    s_scale[t] = sc;
    s_shift[t] = sh;
    __syncthreads();
}

// ---------------- layer-1 gather (external fp32 x, FI=7 -> padded 8) ---------
__global__ void __launch_bounds__(256) k_gather1(const float* __restrict__ x,
                                                 const float* __restrict__ gam,
                                                 const float* __restrict__ bet) {
    const int FI = 7, FIP = 8, LPN = 8;
    __shared__ float s_scale[256], s_shift[256];
    bn_smem(s_scale, s_shift, FI, 0, gam, bet);

    int gid = blockIdx.x * blockDim.x + threadIdx.x;
    int node = gid / LPN;
    int lane = gid % LPN;
    if (node >= N_NODES) return;
    int beg = g_off[node], end = g_off[node + 1];
    float acc = 0.f, sumw = 0.f;
    int e = beg;
    for (; e + 1 < end; e += 2) {
        int s0 = __ldg(&g_srcarr[e]);
        int s1 = __ldg(&g_srcarr[e + 1]);
        float w0 = __ldg(&g_normarr[e]);
        float w1 = __ldg(&g_normarr[e + 1]);
        sumw += w0 + w1;
        if (lane < FI) {
            float v0 = __ldg(&x[(size_t)s0 * FI + lane]);
            float v1 = __ldg(&x[(size_t)s1 * FI + lane]);
            acc += w0 * v0 + w1 * v1;
        }
    }
    if (e < end) {
        int s = __ldg(&g_srcarr[e]);
        float wn = __ldg(&g_normarr[e]);
        sumw += wn;
        if (lane < FI) acc += wn * __ldg(&x[(size_t)s * FI + lane]);
    }
    float r = s_scale[lane] * acc + s_shift[lane] * sumw;
    g_hA[(size_t)node * FIP + lane] = __float2half_rn(r);
}

// ---------------- fp16 gather: LPN lanes/node, 8 halves (uint4) per lane -----
template <int LPN, bool SRC_B>
__global__ void __launch_bounds__(256) k_gatherh(const float* __restrict__ gam,
                                                 const float* __restrict__ bet,
                                                 int FI, int soff) {
    __shared__ float s_scale[256], s_shift[256];
    bn_smem(s_scale, s_shift, FI, soff, gam, bet);

    int gid = blockIdx.x * blockDim.x + threadIdx.x;
    int node = gid / LPN;
    int lane = gid - node * LPN;
    if (node >= N_NODES) return;
    int beg = g_off[node], end = g_off[node + 1];
    const uint4* in8 = (const uint4*)(SRC_B ? g_hB : g_hA);
    uint4* out8 = (uint4*)(SRC_B ? g_hA : g_hB);
    float acc[8];
    #pragma unroll
    for (int q = 0; q < 8; q++) acc[q] = 0.f;
    float sumw = 0.f;
    int e = beg;
    for (; e + 1 < end; e += 2) {
        int s0 = __ldg(&g_srcarr[e]);
        int s1 = __ldg(&g_srcarr[e + 1]);
        float w0 = __ldg(&g_normarr[e]);
        float w1 = __ldg(&g_normarr[e + 1]);
        sumw += w0 + w1;
        uint4 va = __ldg(&in8[(size_t)s0 * LPN + lane]);
        uint4 vb = __ldg(&in8[(size_t)s1 * LPN + lane]);
        float2 a0 = __half22float2(*(__half2*)&va.x);
        float2 a1 = __half22float2(*(__half2*)&va.y);
        float2 a2 = __half22float2(*(__half2*)&va.z);
        float2 a3 = __half22float2(*(__half2*)&va.w);
        float2 b0 = __half22float2(*(__half2*)&vb.x);
        float2 b1 = __half22float2(*(__half2*)&vb.y);
        float2 b2 = __half22float2(*(__half2*)&vb.z);
        float2 b3 = __half22float2(*(__half2*)&vb.w);
        acc[0] += w0 * a0.x + w1 * b0.x; acc[1] += w0 * a0.y + w1 * b0.y;
        acc[2] += w0 * a1.x + w1 * b1.x; acc[3] += w0 * a1.y + w1 * b1.y;
        acc[4] += w0 * a2.x + w1 * b2.x; acc[5] += w0 * a2.y + w1 * b2.y;
        acc[6] += w0 * a3.x + w1 * b3.x; acc[7] += w0 * a3.y + w1 * b3.y;
    }
    if (e < end) {
        int s = __ldg(&g_srcarr[e]);
        float wn = __ldg(&g_normarr[e]);
        sumw += wn;
        uint4 v = __ldg(&in8[(size_t)s * LPN + lane]);
        float2 f0 = __half22float2(*(__half2*)&v.x);
        float2 f1 = __half22float2(*(__half2*)&v.y);
        float2 f2 = __half22float2(*(__half2*)&v.z);
        float2 f3 = __half22float2(*(__half2*)&v.w);
        acc[0] += wn * f0.x; acc[1] += wn * f0.y;
        acc[2] += wn * f1.x; acc[3] += wn * f1.y;
        acc[4] += wn * f2.x; acc[5] += wn * f2.y;
        acc[6] += wn * f3.x; acc[7] += wn * f3.y;
    }
    int c = lane * 8;
    __half2 h[4];
    #pragma unroll
    for (int q = 0; q < 4; q++) {
        float v0 = s_scale[c + 2 * q]     * acc[2 * q]     + s_shift[c + 2 * q]     * sumw;
        float v1 = s_scale[c + 2 * q + 1] * acc[2 * q + 1] + s_shift[c + 2 * q + 1] * sumw;
        h[q] = __floats2half2_rn(v0, v1);
    }
    uint4 o;
    o.x = *(uint32_t*)&h[0]; o.y = *(uint32_t*)&h[1];
    o.z = *(uint32_t*)&h[2]; o.w = *(uint32_t*)&h[3];
    out8[(size_t)node * LPN + lane] = o;
}

// ---------------- fp16 mma GEMM: out = relu(in @ W + bias) -------------------
// CTA = 64 rows x full FO (NJ chunks of 64 inside; A staged once).
// 8 warps: 2 M x 4 N; warp tile 32x16; mma m16n8k16 f16->f32.
template <int FIP, int KPAD, int FO, int FOP, int NJ, bool STATS, bool SRC_A>
__global__ void __launch_bounds__(256) k_gemm_h(int woff, int soff,
                                                const float* __restrict__ bias) {
    const int SA = KPAD + 8;
    __shared__ __align__(16) __half Asm[64 * SA];
    __shared__ __align__(16) __half Wsm[64 * SA];
    __shared__ float  sred[64];
    __shared__ float  sqred[64];

    int tid = threadIdx.x;
    int wid = tid >> 5, lane = tid & 31;
    int grp = lane >> 2, tg = lane & 3;
    int mwarp = (wid & 1) * 32;
    int nwarp = (wid >> 1) * 16;
    int n0 = blockIdx.x * 64;
    const __half* inb = SRC_A ? g_hA : g_hB;
    __half* outb = SRC_A ? g_hB : g_hA;

    // stage A once
    {
        const int VR = KPAD / 8;
        const uint4* src = (const uint4*)inb;
        for (int idx = tid; idx < 64 * VR; idx += 256) {
            int r = idx / VR, q = idx - r * VR;
            uint4 v = make_uint4(0, 0, 0, 0);
            if (n0 + r < N_NODES && q < FIP / 8)
                v = __ldg(&src[(size_t)(n0 + r) * (FIP / 8) + q]);
            *(uint4*)&Asm[r * SA + q * 8] = v;
        }
    }

    for (int jc = 0; jc < NJ; jc++) {
        int j0 = jc * 64;
        __syncthreads();
        {
            const uint4* wsrc = (const uint4*)(g_Wt + woff + (size_t)jc * 64 * SA);
            uint4* wdst = (uint4*)Wsm;
            #pragma unroll 4
            for (int i = tid; i < 64 * SA / 8; i += 256) wdst[i] = __ldg(&wsrc[i]);
        }
        if (STATS && tid < 64) { sred[tid] = 0.f; sqred[tid] = 0.f; }
        __syncthreads();

        float c[2][2][4];
        #pragma unroll
        for (int mi = 0; mi < 2; mi++)
            #pragma unroll
            for (int ni = 0; ni < 2; ni++)
                #pragma unroll
                for (int q = 0; q < 4; q++) c[mi][ni][q] = 0.f;

        const int NS = KPAD / 16;
        #pragma unroll
        for (int ks = 0; ks < NS; ks++) {
            int kb = ks * 16;
            uint32_t a[2][4];
            #pragma unroll
            for (int mi = 0; mi < 2; mi++) {
                int row = mwarp + mi * 16 + grp;
                const __half* ap = &Asm[row * SA + kb + 2 * tg];
                a[mi][0] = *(const uint32_t*)ap;
                a[mi][1] = *(const uint32_t*)(ap + 8 * SA);
                a[mi][2] = *(const uint32_t*)(ap + 8);
                a[mi][3] = *(const uint32_t*)(ap + 8 * SA + 8);
            }
            uint32_t b[2][2];
            #pragma unroll
            for (int ni = 0; ni < 2; ni++) {
                int nn = nwarp + ni * 8 + grp;
                const __half* bp = &Wsm[nn * SA + kb + 2 * tg];
                b[ni][0] = *(const uint32_t*)bp;
                b[ni][1] = *(const uint32_t*)(bp + 8);
            }
            #pragma unroll
            for (int mi = 0; mi < 2; mi++)
                #pragma unroll
                for (int ni = 0; ni < 2; ni++) {
                    asm volatile(
                        "mma.sync.aligned.m16n8k16.row.col.f32.f16.f16.f32 "
                        "{%0,%1,%2,%3}, {%4,%5,%6,%7}, {%8,%9}, {%0,%1,%2,%3};"
                        : "+f"(c[mi][ni][0]), "+f"(c[mi][ni][1]),
                          "+f"(c[mi][ni][2]), "+f"(c[mi][ni][3])
                        : "r"(a[mi][0]), "r"(a[mi][1]), "r"(a[mi][2]), "r"(a[mi][3]),
                          "r"(b[ni][0]), "r"(b[ni][1]));
                }
        }

        #pragma unroll
        for (int mi = 0; mi < 2; mi++) {
            int r0 = n0 + mwarp + mi * 16 + grp;
            int r1 = r0 + 8;
            #pragma unroll
            for (int ni = 0; ni < 2; ni++) {
                int jb = j0 + nwarp + ni * 8 + 2 * tg;
                if (jb >= FO) continue;
                float bj0 = __ldg(&bias[jb]);
                float bj1 = (jb + 1 < FO) ? __ldg(&bias[jb + 1]) : 0.f;
                float v00 = c[mi][ni][0] + bj0; v00 = v00 > 0.f ? v00 : 0.f;
                float v01 = c[mi][ni][1] + bj1; v01 = v01 > 0.f ? v01 : 0.f;
                float v10 = c[mi][ni][2] + bj0; v10 = v10 > 0.f ? v10 : 0.f;
                float v11 = c[mi][ni][3] + bj1; v11 = v11 > 0.f ? v11 : 0.f;
                if (jb + 1 >= FO) { v01 = 0.f; v11 = 0.f; }
                bool ok0 = (r0 < N_NODES), ok1 = (r1 < N_NODES);
                __half2 p0 = __floats2half2_rn(v00, v01);
                __half2 p1 = __floats2half2_rn(v10, v11);
                if (ok0) *(uint32_t*)&outb[(size_t)r0 * FOP + jb] = *(uint32_t*)&p0;
                if (ok1) *(uint32_t*)&outb[(size_t)r1 * FOP + jb] = *(uint32_t*)&p1;
                if (STATS) {
                    float s0 = (ok0 ? v00 : 0.f) + (ok1 ? v10 : 0.f);
                    float q0 = (ok0 ? v00 * v00 : 0.f) + (ok1 ? v10 * v10 : 0.f);
                    float s1 = (ok0 ? v01 : 0.f) + (ok1 ? v11 : 0.f);
                    float q1 = (ok0 ? v01 * v01 : 0.f) + (ok1 ? v11 * v11 : 0.f);
                    int cb = nwarp + ni * 8 + 2 * tg;
                    atomicAdd(&sred[cb], s0);
                    atomicAdd(&sqred[cb], q0);
                    atomicAdd(&sred[cb + 1], s1);
                    atomicAdd(&sqred[cb + 1], q1);
                }
            }
        }
        if (STATS) {
            __syncthreads();
            if (tid < 64) {
                int j = j0 + tid;
                if (j < FO) {
                    atomicAdd(&g_stats[soff + j], sred[tid]);
                    atomicAdd(&g_stats[soff + 256 + j], sqred[tid]);
                }
            }
        }
    }
}

// ---------------- fused mean-pool + MLP head (hB fp16, stride 200) ----------
__global__ void __launch_bounds__(256) k_poolmlp(const float* __restrict__ Wl1,
                                                 const float* __restrict__ bl1,
                                                 const float* __restrict__ Wl2,
                                                 const float* __restrict__ bl2,
                                                 float* __restrict__ out) {
    const int FO = 199, FOP = 200;
    __shared__ float pooled[FO];
    __shared__ float t1[49];
    int g = blockIdx.x;
    int s = g_gstart[g], e = g_gstart[g + 1];
    int f = threadIdx.x;
    if (f < FO) {
        float a0 = 0.f, a1 = 0.f, a2 = 0.f, a3 = 0.f;
        int n = s;
        for (; n + 3 < e; n += 4) {
            a0 += __half2float(__ldg(&g_hB[(size_t)n * FOP + f]));
            a1 += __half2float(__ldg(&g_hB[(size_t)(n + 1) * FOP + f]));
            a2 += __half2float(__ldg(&g_hB[(size_t)(n + 2) * FOP + f]));
            a3 += __half2float(__ldg(&g_hB[(size_t)(n + 3) * FOP + f]));
        }
        for (; n < e; n++) a0 += __half2float(__ldg(&g_hB[(size_t)n * FOP + f]));
        float acc = (a0 + a1) + (a2 + a3);
        int cnt = e - s;
        pooled[f] = acc / (float)(cnt > 0 ? cnt : 1);
    }
    __syncthreads();
    if (f < 49) {
        float a = bl1[f];
        for (int k = 0; k < FO; k++) a += pooled[k] * Wl1[k * 49 + f];
        t1[f] = a;
    }
    __syncthreads();
    if (f < 2) {
        float a = bl2[f];
        for (int k = 0; k < 49; k++) a += t1[k] * Wl2[k * 2 + f];
        out[g * 2 + f] = a;
    }
}

// ---------------- launch ----------------
extern "C" void kernel_launch(void* const* d_in, const int* in_sizes, int n_in,
                              void* d_out, int out_size) {
    const float* x     = (const float*)d_in[0];
    const void*  ei    = d_in[1];
    const void*  batch = d_in[2];
    const float* bn0g = (const float*)d_in[3];
    const float* bn0b = (const float*)d_in[4];
    const float* bn1g = (const float*)d_in[5];
    const float* bn1b = (const float*)d_in[6];
    const float* bn2g = (const float*)d_in[7];
    const float* bn2b = (const float*)d_in[8];
    const float* W1  = (const float*)d_in[9];
    const float* b1  = (const float*)d_in[10];
    const float* W2  = (const float*)d_in[11];
    const float* b2  = (const float*)d_in[12];
    const float* W3  = (const float*)d_in[13];
    const float* b3  = (const float*)d_in[14];
    const float* Wl1 = (const float*)d_in[15];
    const float* bl1 = (const float*)d_in[16];
    const float* Wl2 = (const float*)d_in[17];
    const float* bl2 = (const float*)d_in[18];
    float* out = (float*)d_out;

    const int NB_N = (N_NODES + 255) / 256;
    const int NB_E = (N_EDGES + 255) / 256;

    // graph preprocessing
    k_init<<<NB_N, 256>>>((const int*)ei);
    k_deg_edges<<<NB_E, 256>>>(ei);
    k_scan1<<<SCAN_BLOCKS, 256>>>();
    k_scan2<<<1, 256>>>();
    k_scan3<<<NB_N, 256>>>(batch);
    k_fill<<<NB_E, 256>>>(ei);

    // pre-convert weights (single launch)
    k_wprep_all<<<9, 256>>>(W1, W2, W3);

    dim3 sblk(32, 8);
    const int NB_G8  = ((N_NODES * 8)  + 255) / 256;
    const int NB_G9  = ((N_NODES * 9)  + 255) / 256;
    const int NB_G17 = ((N_NODES * 17) + 255) / 256;
    const int GX64 = N_PAD / 64;

    // ---- layer 1: stats buf0 -> gather1(BN0) -> gemm (stats -> buf1)
    k_stats_x<<<dim3(1, 64), sblk>>>(x, 7);
    k_gather1<<<NB_G8, 256>>>(x, bn0g, bn0b);
    k_gemm_h<8, 16, 71, 72, 2, true, true><<<GX64, 256>>>(0, 512, b1);

    // ---- layer 2: gatherh(BN1 from buf1) hB->hA -> gemm (stats -> buf2)
    k_gatherh<9, true><<<NB_G9, 256>>>(bn1g, bn1b, 71, 512);
    k_gemm_h<72, 80, 135, 136, 3, true, true><<<GX64, 256>>>(3072, 1024, b2);

    // ---- layer 3: gatherh(BN2 from buf2) hB->hA -> gemm (no stats)
    k_gatherh<17, true><<<NB_G17, 256>>>(bn2g, bn2b, 135, 1024);
    k_gemm_h<136, 144, 199, 200, 4, false, true><<<GX64, 256>>>(19968, 0, b3);

    // ---- pool + head
    k_poolmlp<<<N_GRAPHS, 256>>>(Wl1, bl1, Wl2, bl2, out);
}

// round 15
// speedup vs baseline: 1.0928x; 1.0160x over previous
#include <cuda_runtime.h>
#include <cuda_fp16.h>
#include <math.h>
#include <stdint.h>

#define N_NODES 100000
#define N_PAD   100096   // multiple of 128
#define N_EDGES 1600000
#define N_TOT   1700000
#define N_GRAPHS 256
#define BN_EPS 1e-5f

// ---------------- scratch (device globals; no runtime allocation) -------------
__device__ int    g_idx64;
__device__ int    g_ctr;
__device__ int    g_deg[N_NODES];
__device__ float  g_dinv[N_NODES];
__device__ int    g_off[N_NODES];
__device__ int    g_cursor[N_NODES];
__device__ int    g_srcarr[N_TOT];
__device__ float  g_normarr[N_TOT];
__device__ __half g_hA[(size_t)N_PAD * 200];
__device__ __half g_hB[(size_t)N_PAD * 200];
__device__ float  g_stats[3 * 512];   // per-layer: [soff+0..255]=sum, [soff+256..511]=sumsq
__device__ float  g_pooled[N_GRAPHS * 200];
__device__ int    g_gstart[N_GRAPHS + 1];
// pre-converted fp16 weights, transposed [n][k], per-chunk stride SA=KPAD+8
__device__ __align__(16) __half g_Wt[58880];

__device__ __forceinline__ int idx_at(const void* p, long i, int is64) {
    if (is64) return (int)((const long long*)p)[i];
    return ((const int*)p)[i];
}

// ---------------- init ----------------
__global__ void __launch_bounds__(256) k_init(const int* __restrict__ ei32) {
    int n = blockIdx.x * blockDim.x + threadIdx.x;
    if (n < N_NODES) g_deg[n] = 1;
    if (n < 3 * 512) g_stats[n] = 0.0f;
    if (n < N_GRAPHS * 200) g_pooled[n] = 0.0f;
    if (n == 0) {
        g_ctr = 0;
        int any = 0;
        for (int k = 0; k < 64; k++)
            if (ei32[2 * k + 1] != 0) { any = 1; break; }
        g_idx64 = !any;
    }
}

__global__ void __launch_bounds__(256) k_deg_edges(const void* __restrict__ ei) {
    int e = blockIdx.x * blockDim.x + threadIdx.x;
    if (e < N_EDGES) {
        int is64 = g_idx64;
        int d = idx_at(ei, (long)N_EDGES + e, is64);
        if ((unsigned)d < N_NODES) atomicAdd(&g_deg[d], 1);
    }
}

// single-pass offset assignment: block-local scan + one atomicAdd per block.
// CSR regions are contiguous per node but NOT node-ordered (gathers use off+deg).
// Also: dinv, self-loop entry, cursor init, graph-boundary scatter.
__global__ void __launch_bounds__(256) k_assign(const void* __restrict__ batch) {
    __shared__ int sh[256];
    __shared__ int s_base;
    int t = threadIdx.x;
    int n = blockIdx.x * 256 + t;
    int dg = 0;
    float di = 0.f;
    if (n < N_NODES) {
        dg = g_deg[n];
        di = rsqrtf((float)dg);
        g_dinv[n] = di;
    }
    sh[t] = dg;
    __syncthreads();
    for (int o = 1; o < 256; o <<= 1) {
        int v = (t >= o) ? sh[t - o] : 0;
        __syncthreads();
        sh[t] += v;
        __syncthreads();
    }
    if (t == 255) s_base = atomicAdd(&g_ctr, sh[255]);
    __syncthreads();
    if (n < N_NODES) {
        int o = s_base + sh[t] - dg;
        g_off[n] = o;
        g_srcarr[o] = n;
        g_normarr[o] = di * di;
        g_cursor[n] = o + 1;
        int is64 = g_idx64;
        int b1 = idx_at(batch, n, is64);
        if (b1 >= 0 && b1 < N_GRAPHS) {
            int b0 = (n == 0) ? -1 : idx_at(batch, n - 1, is64);
            for (int g = b0 + 1; g <= b1; g++) g_gstart[g] = n;
            if (n == N_NODES - 1)
                for (int g = b1 + 1; g <= N_GRAPHS; g++) g_gstart[g] = N_NODES;
        }
    }
}

__global__ void __launch_bounds__(256) k_fill(const void* __restrict__ ei) {
    int e = blockIdx.x * blockDim.x + threadIdx.x;
    if (e < N_EDGES) {
        int is64 = g_idx64;
        int s = idx_at(ei, e, is64);
        int d = idx_at(ei, (long)N_EDGES + e, is64);
        if ((unsigned)s < N_NODES && (unsigned)d < N_NODES) {
            int pos = atomicAdd(&g_cursor[d], 1);
            if ((unsigned)pos < N_TOT) {
                g_srcarr[pos] = s;
                g_normarr[pos] = g_dinv[s] * g_dinv[d];
            }
        }
    }
}

// ---------------- W pre-conversion (all 3 layers in one launch, 9 blocks) ----
__global__ void __launch_bounds__(256) k_wprep_all(const float* __restrict__ W1,
                                                   const float* __restrict__ W2,
                                                   const float* __restrict__ W3) {
    int b = blockIdx.x;
    const float* W; int FI, KPAD, FO, off, jc;
    if (b < 2)      { W = W1; FI = 7;   KPAD = 16;  FO = 71;  off = 0;     jc = b; }
    else if (b < 5) { W = W2; FI = 71;  KPAD = 80;  FO = 135; off = 3072;  jc = b - 2; }
    else            { W = W3; FI = 135; KPAD = 144; FO = 199; off = 19968; jc = b - 5; }
    int SA = KPAD + 8;
    int j0 = jc * 64;
    __half* dst = g_Wt + off + jc * 64 * SA;
    for (int idx = threadIdx.x; idx < 64 * SA; idx += 256) {
        int nn = idx / SA, k = idx - nn * SA;
        float v = (k < FI && (j0 + nn) < FO) ? __ldg(&W[k * FO + j0 + nn]) : 0.f;
        dst[idx] = __float2half_rn(v);
    }
}

// ---------------- stats over external x (layer 0 only, into buffer 0) --------
__global__ void __launch_bounds__(256) k_stats_x(const float* __restrict__ x, int FI) {
    int f = threadIdx.x;
    float s = 0.f, sq = 0.f;
    if (f < FI) {
        for (int n = blockIdx.y * blockDim.y + threadIdx.y; n < N_NODES;
             n += gridDim.y * blockDim.y) {
            float v = x[(size_t)n * FI + f];
            s += v;
            sq += v * v;
        }
    }
    __shared__ float shs[8][32];
    __shared__ float shq[8][32];
    shs[threadIdx.y][threadIdx.x] = s;
    shq[threadIdx.y][threadIdx.x] = sq;
    __syncthreads();
    if (threadIdx.y == 0 && f < FI) {
        float ts = 0.f, tq = 0.f;
        #pragma unroll
        for (int y = 0; y < 8; y++) { ts += shs[y][threadIdx.x]; tq += shq[y][threadIdx.x]; }
        atomicAdd(&g_stats[f], ts);
        atomicAdd(&g_stats[256 + f], tq);
    }
}

// per-block BN finalize into smem
__device__ __forceinline__ void bn_smem(float* s_scale, float* s_shift, int FI, int soff,
                                        const float* gam, const float* bet) {
    int t = threadIdx.x;
    float sc = 0.f, sh = 0.f;
    if (t < FI) {
        float m = g_stats[soff + t] * (1.0f / N_NODES);
        float v = g_stats[soff + 256 + t] * (1.0f / N_NODES) - m * m;
        float a = __ldg(&gam[t]) * rsqrtf(v + BN_EPS);
        sc = a;
        sh = __ldg(&bet[t]) - m * a;
    }
    s_scale[t] = sc;
    s_shift[t] = sh;
    __syncthreads();
}

// ---------------- layer-1 gather (external fp32 x, FI=7 -> padded 8) ---------
__global__ void __launch_bounds__(256) k_gather1(const float* __restrict__ x,
                                                 const float* __restrict__ gam,
                                                 const float* __restrict__ bet) {
    const int FI = 7, FIP = 8, LPN = 8;
    __shared__ float s_scale[256], s_shift[256];
    bn_smem(s_scale, s_shift, FI, 0, gam, bet);

    int gid = blockIdx.x * blockDim.x + threadIdx.x;
    int node = gid / LPN;
    int lane = gid % LPN;
    if (node >= N_NODES) return;
    int beg = __ldg(&g_off[node]);
    int end = beg + __ldg(&g_deg[node]);
    float acc = 0.f, sumw = 0.f;
    int e = beg;
    for (; e + 1 < end; e += 2) {
        int s0 = __ldg(&g_srcarr[e]);
        int s1 = __ldg(&g_srcarr[e + 1]);
        float w0 = __ldg(&g_normarr[e]);
        float w1 = __ldg(&g_normarr[e + 1]);
        sumw += w0 + w1;
        if (lane < FI) {
            float v0 = __ldg(&x[(size_t)s0 * FI + lane]);
            float v1 = __ldg(&x[(size_t)s1 * FI + lane]);
            acc += w0 * v0 + w1 * v1;
        }
    }
    if (e < end) {
        int s = __ldg(&g_srcarr[e]);
        float wn = __ldg(&g_normarr[e]);
        sumw += wn;
        if (lane < FI) acc += wn * __ldg(&x[(size_t)s * FI + lane]);
    }
    float r = s_scale[lane] * acc + s_shift[lane] * sumw;
    g_hA[(size_t)node * FIP + lane] = __float2half_rn(r);
}

// ---------------- fp16 gather: LPN lanes/node, 8 halves (uint4) per lane -----
template <int LPN, bool SRC_B>
__global__ void __launch_bounds__(256) k_gatherh(const float* __restrict__ gam,
                                                 const float* __restrict__ bet,
                                                 int FI, int soff) {
    __shared__ float s_scale[256], s_shift[256];
    bn_smem(s_scale, s_shift, FI, soff, gam, bet);

    int gid = blockIdx.x * blockDim.x + threadIdx.x;
    int node = gid / LPN;
    int lane = gid - node * LPN;
    if (node >= N_NODES) return;
    int beg = __ldg(&g_off[node]);
    int end = beg + __ldg(&g_deg[node]);
    const uint4* in8 = (const uint4*)(SRC_B ? g_hB : g_hA);
    uint4* out8 = (uint4*)(SRC_B ? g_hA : g_hB);
    float acc[8];
    #pragma unroll
    for (int q = 0; q < 8; q++) acc[q] = 0.f;
    float sumw = 0.f;
    int e = beg;
    for (; e + 1 < end; e += 2) {
        int s0 = __ldg(&g_srcarr[e]);
        int s1 = __ldg(&g_srcarr[e + 1]);
        float w0 = __ldg(&g_normarr[e]);
        float w1 = __ldg(&g_normarr[e + 1]);
        sumw += w0 + w1;
        uint4 va = __ldg(&in8[(size_t)s0 * LPN + lane]);
        uint4 vb = __ldg(&in8[(size_t)s1 * LPN + lane]);
        float2 a0 = __half22float2(*(__half2*)&va.x);
        float2 a1 = __half22float2(*(__half2*)&va.y);
        float2 a2 = __half22float2(*(__half2*)&va.z);
        float2 a3 = __half22float2(*(__half2*)&va.w);
        float2 b0 = __half22float2(*(__half2*)&vb.x);
        float2 b1 = __half22float2(*(__half2*)&vb.y);
        float2 b2 = __half22float2(*(__half2*)&vb.z);
        float2 b3 = __half22float2(*(__half2*)&vb.w);
        acc[0] += w0 * a0.x + w1 * b0.x; acc[1] += w0 * a0.y + w1 * b0.y;
        acc[2] += w0 * a1.x + w1 * b1.x; acc[3] += w0 * a1.y + w1 * b1.y;
        acc[4] += w0 * a2.x + w1 * b2.x; acc[5] += w0 * a2.y + w1 * b2.y;
        acc[6] += w0 * a3.x + w1 * b3.x; acc[7] += w0 * a3.y + w1 * b3.y;
    }
    if (e < end) {
        int s = __ldg(&g_srcarr[e]);
        float wn = __ldg(&g_normarr[e]);
        sumw += wn;
        uint4 v = __ldg(&in8[(size_t)s * LPN + lane]);
        float2 f0 = __half22float2(*(__half2*)&v.x);
        float2 f1 = __half22float2(*(__half2*)&v.y);
        float2 f2 = __half22float2(*(__half2*)&v.z);
        float2 f3 = __half22float2(*(__half2*)&v.w);
        acc[0] += wn * f0.x; acc[1] += wn * f0.y;
        acc[2] += wn * f1.x; acc[3] += wn * f1.y;
        acc[4] += wn * f2.x; acc[5] += wn * f2.y;
        acc[6] += wn * f3.x; acc[7] += wn * f3.y;
    }
    int c = lane * 8;
    __half2 h[4];
    #pragma unroll
    for (int q = 0; q < 4; q++) {
        float v0 = s_scale[c + 2 * q]     * acc[2 * q]     + s_shift[c + 2 * q]     * sumw;
        float v1 = s_scale[c + 2 * q + 1] * acc[2 * q + 1] + s_shift[c + 2 * q + 1] * sumw;
        h[q] = __floats2half2_rn(v0, v1);
    }
    uint4 o;
    o.x = *(uint32_t*)&h[0]; o.y = *(uint32_t*)&h[1];
    o.z = *(uint32_t*)&h[2]; o.w = *(uint32_t*)&h[3];
    out8[(size_t)node * LPN + lane] = o;
}

// ---------------- fp16 mma GEMM: out = relu(in @ W + bias) -------------------
template <int FIP, int KPAD, int FO, int FOP, int NJ, bool STATS, bool SRC_A>
__global__ void __launch_bounds__(256) k_gemm_h(int woff, int soff,
                                                const float* __restrict__ bias) {
    const int SA = KPAD + 8;
    __shared__ __align__(16) __half Asm[64 * SA];
    __shared__ __align__(16) __half Wsm[64 * SA];
    __shared__ float  sred[64];
    __shared__ float  sqred[64];

    int tid = threadIdx.x;
    int wid = tid >> 5, lane = tid & 31;
    int grp = lane >> 2, tg = lane & 3;
    int mwarp = (wid & 1) * 32;
    int nwarp = (wid >> 1) * 16;
    int n0 = blockIdx.x * 64;
    const __half* inb = SRC_A ? g_hA : g_hB;
    __half* outb = SRC_A ? g_hB : g_hA;

    // stage A once
    {
        const int VR = KPAD / 8;
        const uint4* src = (const uint4*)inb;
        for (int idx = tid; idx < 64 * VR; idx += 256) {
            int r = idx / VR, q = idx - r * VR;
            uint4 v = make_uint4(0, 0, 0, 0);
            if (n0 + r < N_NODES && q < FIP / 8)
                v = __ldg(&src[(size_t)(n0 + r) * (FIP / 8) + q]);
            *(uint4*)&Asm[r * SA + q * 8] = v;
        }
    }

    for (int jc = 0; jc < NJ; jc++) {
        int j0 = jc * 64;
        __syncthreads();
        {
            const uint4* wsrc = (const uint4*)(g_Wt + woff + (size_t)jc * 64 * SA);
            uint4* wdst = (uint4*)Wsm;
            #pragma unroll 4
            for (int i = tid; i < 64 * SA / 8; i += 256) wdst[i] = __ldg(&wsrc[i]);
        }
        if (STATS && tid < 64) { sred[tid] = 0.f; sqred[tid] = 0.f; }
        __syncthreads();

        float c[2][2][4];
        #pragma unroll
        for (int mi = 0; mi < 2; mi++)
            #pragma unroll
            for (int ni = 0; ni < 2; ni++)
                #pragma unroll
                for (int q = 0; q < 4; q++) c[mi][ni][q] = 0.f;

        const int NS = KPAD / 16;
        #pragma unroll
        for (int ks = 0; ks < NS; ks++) {
            int kb = ks * 16;
            uint32_t a[2][4];
            #pragma unroll
            for (int mi = 0; mi < 2; mi++) {
                int row = mwarp + mi * 16 + grp;
                const __half* ap = &Asm[row * SA + kb + 2 * tg];
                a[mi][0] = *(const uint32_t*)ap;
                a[mi][1] = *(const uint32_t*)(ap + 8 * SA);
                a[mi][2] = *(const uint32_t*)(ap + 8);
                a[mi][3] = *(const uint32_t*)(ap + 8 * SA + 8);
            }
            uint32_t b[2][2];
            #pragma unroll
            for (int ni = 0; ni < 2; ni++) {
                int nn = nwarp + ni * 8 + grp;
                const __half* bp = &Wsm[nn * SA + kb + 2 * tg];
                b[ni][0] = *(const uint32_t*)bp;
                b[ni][1] = *(const uint32_t*)(bp + 8);
            }
            #pragma unroll
            for (int mi = 0; mi < 2; mi++)
                #pragma unroll
                for (int ni = 0; ni < 2; ni++) {
                    asm volatile(
                        "mma.sync.aligned.m16n8k16.row.col.f32.f16.f16.f32 "
                        "{%0,%1,%2,%3}, {%4,%5,%6,%7}, {%8,%9}, {%0,%1,%2,%3};"
                        : "+f"(c[mi][ni][0]), "+f"(c[mi][ni][1]),
                          "+f"(c[mi][ni][2]), "+f"(c[mi][ni][3])
                        : "r"(a[mi][0]), "r"(a[mi][1]), "r"(a[mi][2]), "r"(a[mi][3]),
                          "r"(b[ni][0]), "r"(b[ni][1]));
                }
        }

        #pragma unroll
        for (int mi = 0; mi < 2; mi++) {
            int r0 = n0 + mwarp + mi * 16 + grp;
            int r1 = r0 + 8;
            #pragma unroll
            for (int ni = 0; ni < 2; ni++) {
                int jb = j0 + nwarp + ni * 8 + 2 * tg;
                if (jb >= FO) continue;
                float bj0 = __ldg(&bias[jb]);
                float bj1 = (jb + 1 < FO) ? __ldg(&bias[jb + 1]) : 0.f;
                float v00 = c[mi][ni][0] + bj0; v00 = v00 > 0.f ? v00 : 0.f;
                float v01 = c[mi][ni][1] + bj1; v01 = v01 > 0.f ? v01 : 0.f;
                float v10 = c[mi][ni][2] + bj0; v10 = v10 > 0.f ? v10 : 0.f;
                float v11 = c[mi][ni][3] + bj1; v11 = v11 > 0.f ? v11 : 0.f;
                if (jb + 1 >= FO) { v01 = 0.f; v11 = 0.f; }
                bool ok0 = (r0 < N_NODES), ok1 = (r1 < N_NODES);
                __half2 p0 = __floats2half2_rn(v00, v01);
                __half2 p1 = __floats2half2_rn(v10, v11);
                if (ok0) *(uint32_t*)&outb[(size_t)r0 * FOP + jb] = *(uint32_t*)&p0;
                if (ok1) *(uint32_t*)&outb[(size_t)r1 * FOP + jb] = *(uint32_t*)&p1;
                if (STATS) {
                    float s0 = (ok0 ? v00 : 0.f) + (ok1 ? v10 : 0.f);
                    float q0 = (ok0 ? v00 * v00 : 0.f) + (ok1 ? v10 * v10 : 0.f);
                    float s1 = (ok0 ? v01 : 0.f) + (ok1 ? v11 : 0.f);
                    float q1 = (ok0 ? v01 * v01 : 0.f) + (ok1 ? v11 * v11 : 0.f);
                    int cb = nwarp + ni * 8 + 2 * tg;
                    atomicAdd(&sred[cb], s0);
                    atomicAdd(&sqred[cb], q0);
                    atomicAdd(&sred[cb + 1], s1);
                    atomicAdd(&sqred[cb + 1], q1);
                }
            }
        }
        if (STATS) {
            __syncthreads();
            if (tid < 64) {
                int j = j0 + tid;
                if (j < FO) {
                    atomicAdd(&g_stats[soff + j], sred[tid]);
                    atomicAdd(&g_stats[soff + 256 + j], sqred[tid]);
                }
            }
        }
    }
}

// ---------------- pool partial sums: grid (N_GRAPHS, 4) ----------------------
__global__ void __launch_bounds__(256) k_poolpart() {
    const int FO = 199, FOP = 200;
    int g = blockIdx.x;
    int slice = blockIdx.y;
    int s = g_gstart[g], e = g_gstart[g + 1];
    int cnt = e - s;
    if (cnt <= 0) return;
    int per = (cnt + 3) / 4;
    int rs = s + slice * per;
    int re = rs + per;
    if (re > e) re = e;
    if (rs >= re) return;
    int f = threadIdx.x;
    if (f < FO) {
        float a0 = 0.f, a1 = 0.f;
        int n = rs;
        for (; n + 1 < re; n += 2) {
            a0 += __half2float(__ldg(&g_hB[(size_t)n * FOP + f]));
            a1 += __half2float(__ldg(&g_hB[(size_t)(n + 1) * FOP + f]));
        }
        if (n < re) a0 += __half2float(__ldg(&g_hB[(size_t)n * FOP + f]));
        atomicAdd(&g_pooled[g * FOP + f], a0 + a1);
    }
}

// ---------------- MLP head ----------------------------------------------------
__global__ void __launch_bounds__(256) k_mlp(const float* __restrict__ Wl1,
                                             const float* __restrict__ bl1,
                                             const float* __restrict__ Wl2,
                                             const float* __restrict__ bl2,
                                             float* __restrict__ out) {
    const int FO = 199, FOP = 200;
    __shared__ float pooled[FO];
    __shared__ float t1[49];
    int g = blockIdx.x;
    int f = threadIdx.x;
    if (f < FO) {
        int cnt = g_gstart[g + 1] - g_gstart[g];
        pooled[f] = g_pooled[g * FOP + f] / (float)(cnt > 0 ? cnt : 1);
    }
    __syncthreads();
    if (f < 49) {
        float a = bl1[f];
        for (int k = 0; k < FO; k++) a += pooled[k] * Wl1[k * 49 + f];
        t1[f] = a;
    }
    __syncthreads();
    if (f < 2) {
        float a = bl2[f];
        for (int k = 0; k < 49; k++) a += t1[k] * Wl2[k * 2 + f];
        out[g * 2 + f] = a;
    }
}

// ---------------- launch ----------------
extern "C" void kernel_launch(void* const* d_in, const int* in_sizes, int n_in,
                              void* d_out, int out_size) {
    const float* x     = (const float*)d_in[0];
    const void*  ei    = d_in[1];
    const void*  batch = d_in[2];
    const float* bn0g = (const float*)d_in[3];
    const float* bn0b = (const float*)d_in[4];
    const float* bn1g = (const float*)d_in[5];
    const float* bn1b = (const float*)d_in[6];
    const float* bn2g = (const float*)d_in[7];
    const float* bn2b = (const float*)d_in[8];
    const float* W1  = (const float*)d_in[9];
    const float* b1  = (const float*)d_in[10];
    const float* W2  = (const float*)d_in[11];
    const float* b2  = (const float*)d_in[12];
    const float* W3  = (const float*)d_in[13];
    const float* b3  = (const float*)d_in[14];
    const float* Wl1 = (const float*)d_in[15];
    const float* bl1 = (const float*)d_in[16];
    const float* Wl2 = (const float*)d_in[17];
    const float* bl2 = (const float*)d_in[18];
    float* out = (float*)d_out;

    const int NB_N = (N_NODES + 255) / 256;
    const int NB_E = (N_EDGES + 255) / 256;

    // graph preprocessing
    k_init<<<NB_N, 256>>>((const int*)ei);
    k_deg_edges<<<NB_E, 256>>>(ei);
    k_assign<<<NB_N, 256>>>(batch);
    k_fill<<<NB_E, 256>>>(ei);

    // pre-convert weights (single launch)
    k_wprep_all<<<9, 256>>>(W1, W2, W3);

    dim3 sblk(32, 8);
    const int NB_G8  = ((N_NODES * 8)  + 255) / 256;
    const int NB_G9  = ((N_NODES * 9)  + 255) / 256;
    const int NB_G17 = ((N_NODES * 17) + 255) / 256;
    const int GX64 = N_PAD / 64;

    // ---- layer 1: stats buf0 -> gather1(BN0) -> gemm (stats -> buf1)
    k_stats_x<<<dim3(1, 64), sblk>>>(x, 7);
    k_gather1<<<NB_G8, 256>>>(x, bn0g, bn0b);
    k_gemm_h<8, 16, 71, 72, 2, true, true><<<GX64, 256>>>(0, 512, b1);

    // ---- layer 2: gatherh(BN1 from buf1) hB->hA -> gemm (stats -> buf2)
    k_gatherh<9, true><<<NB_G9, 256>>>(bn1g, bn1b, 71, 512);
    k_gemm_h<72, 80, 135, 136, 3, true, true><<<GX64, 256>>>(3072, 1024, b2);

    // ---- layer 3: gatherh(BN2 from buf2) hB->hA -> gemm (no stats)
    k_gatherh<17, true><<<NB_G17, 256>>>(bn2g, bn2b, 135, 1024);
    k_gemm_h<136, 144, 199, 200, 4, false, true><<<GX64, 256>>>(19968, 0, b3);

    // ---- pool + head
    k_poolpart<<<dim3(N_GRAPHS, 4), 256>>>();
    k_mlp<<<N_GRAPHS, 256>>>(Wl1, bl1, Wl2, bl2, out);
}

// round 16
// speedup vs baseline: 1.1139x; 1.0193x over previous
#include <cuda_runtime.h>
#include <cuda_fp16.h>
#include <math.h>
#include <stdint.h>

#define N_NODES 100000
#define N_PAD   100096   // multiple of 128
#define N_EDGES 1600000
#define N_TOT   1700000
#define N_GRAPHS 256
#define BN_EPS 1e-5f

// ---------------- scratch (device globals; no runtime allocation) -------------
__device__ int    g_idx64;
__device__ int    g_ctr;
__device__ int    g_deg[N_NODES];
__device__ float  g_dinv[N_NODES];
__device__ int    g_off[N_NODES];
__device__ int    g_cursor[N_NODES];
__device__ int    g_srcarr[N_TOT];
__device__ __half g_hA[(size_t)N_PAD * 200];
__device__ __half g_hB[(size_t)N_PAD * 200];
__device__ float  g_stats[3 * 512];   // per-layer: [soff+0..255]=sum, [soff+256..511]=sumsq
__device__ float  g_pooled[N_GRAPHS * 200];
__device__ int    g_gstart[N_GRAPHS + 1];
// pre-converted fp16 weights, transposed [n][k], per-chunk stride SA=KPAD+8
__device__ __align__(16) __half g_Wt[58880];

__device__ __forceinline__ int idx_at(const void* p, long i, int is64) {
    if (is64) return (int)((const long long*)p)[i];
    return ((const int*)p)[i];
}

// ---------------- init ----------------
__global__ void __launch_bounds__(256) k_init(const int* __restrict__ ei32) {
    int n = blockIdx.x * blockDim.x + threadIdx.x;
    if (n < N_NODES) g_deg[n] = 1;
    if (n < 3 * 512) g_stats[n] = 0.0f;
    if (n < N_GRAPHS * 200) g_pooled[n] = 0.0f;
    if (n == 0) {
        g_ctr = 0;
        int any = 0;
        for (int k = 0; k < 64; k++)
            if (ei32[2 * k + 1] != 0) { any = 1; break; }
        g_idx64 = !any;
    }
}

__global__ void __launch_bounds__(256) k_deg_edges(const void* __restrict__ ei) {
    int e = blockIdx.x * blockDim.x + threadIdx.x;
    if (e < N_EDGES) {
        int is64 = g_idx64;
        int d = idx_at(ei, (long)N_EDGES + e, is64);
        if ((unsigned)d < N_NODES) atomicAdd(&g_deg[d], 1);
    }
}

// single-pass offset assignment: block-local scan + one atomicAdd per block.
// CSR regions are contiguous per node but NOT node-ordered (gathers use off+deg).
// Also: dinv, self-loop entry, cursor init, graph-boundary scatter.
__global__ void __launch_bounds__(256) k_assign(const void* __restrict__ batch) {
    __shared__ int sh[256];
    __shared__ int s_base;
    int t = threadIdx.x;
    int n = blockIdx.x * 256 + t;
    int dg = 0;
    float di = 0.f;
    if (n < N_NODES) {
        dg = g_deg[n];
        di = rsqrtf((float)dg);
        g_dinv[n] = di;
    }
    sh[t] = dg;
    __syncthreads();
    for (int o = 1; o < 256; o <<= 1) {
        int v = (t >= o) ? sh[t - o] : 0;
        __syncthreads();
        sh[t] += v;
        __syncthreads();
    }
    if (t == 255) s_base = atomicAdd(&g_ctr, sh[255]);
    __syncthreads();
    if (n < N_NODES) {
        int o = s_base + sh[t] - dg;
        g_off[n] = o;
        g_srcarr[o] = n;     // self loop (weight dinv[n]*dinv[n] computed in gather)
        g_cursor[n] = o + 1;
        int is64 = g_idx64;
        int b1 = idx_at(batch, n, is64);
        if (b1 >= 0 && b1 < N_GRAPHS) {
            int b0 = (n == 0) ? -1 : idx_at(batch, n - 1, is64);
            for (int g = b0 + 1; g <= b1; g++) g_gstart[g] = n;
            if (n == N_NODES - 1)
                for (int g = b1 + 1; g <= N_GRAPHS; g++) g_gstart[g] = N_NODES;
        }
    }
}

// fill: indices only (norm weights computed in gathers from dinv)
__global__ void __launch_bounds__(256) k_fill(const void* __restrict__ ei) {
    int e = blockIdx.x * blockDim.x + threadIdx.x;
    if (e < N_EDGES) {
        int is64 = g_idx64;
        int s = idx_at(ei, e, is64);
        int d = idx_at(ei, (long)N_EDGES + e, is64);
        if ((unsigned)s < N_NODES && (unsigned)d < N_NODES) {
            int pos = atomicAdd(&g_cursor[d], 1);
            if ((unsigned)pos < N_TOT) g_srcarr[pos] = s;
        }
    }
}

// ---------------- W pre-conversion (all 3 layers in one launch, 9 blocks) ----
__global__ void __launch_bounds__(256) k_wprep_all(const float* __restrict__ W1,
                                                   const float* __restrict__ W2,
                                                   const float* __restrict__ W3) {
    int b = blockIdx.x;
    const float* W; int FI, KPAD, FO, off, jc;
    if (b < 2)      { W = W1; FI = 7;   KPAD = 16;  FO = 71;  off = 0;     jc = b; }
    else if (b < 5) { W = W2; FI = 71;  KPAD = 80;  FO = 135; off = 3072;  jc = b - 2; }
    else            { W = W3; FI = 135; KPAD = 144; FO = 199; off = 19968; jc = b - 5; }
    int SA = KPAD + 8;
    int j0 = jc * 64;
    __half* dst = g_Wt + off + jc * 64 * SA;
    for (int idx = threadIdx.x; idx < 64 * SA; idx += 256) {
        int nn = idx / SA, k = idx - nn * SA;
        float v = (k < FI && (j0 + nn) < FO) ? __ldg(&W[k * FO + j0 + nn]) : 0.f;
        dst[idx] = __float2half_rn(v);
    }
}

// ---------------- stats over external x (layer 0 only, into buffer 0) --------
__global__ void __launch_bounds__(256) k_stats_x(const float* __restrict__ x, int FI) {
    int f = threadIdx.x;
    float s = 0.f, sq = 0.f;
    if (f < FI) {
        for (int n = blockIdx.y * blockDim.y + threadIdx.y; n < N_NODES;
             n += gridDim.y * blockDim.y) {
            float v = x[(size_t)n * FI + f];
            s += v;
            sq += v * v;
        }
    }
    __shared__ float shs[8][32];
    __shared__ float shq[8][32];
    shs[threadIdx.y][threadIdx.x] = s;
    shq[threadIdx.y][threadIdx.x] = sq;
    __syncthreads();
    if (threadIdx.y == 0 && f < FI) {
        float ts = 0.f, tq = 0.f;
        #pragma unroll
        for (int y = 0; y < 8; y++) { ts += shs[y][threadIdx.x]; tq += shq[y][threadIdx.x]; }
        atomicAdd(&g_stats[f], ts);
        atomicAdd(&g_stats[256 + f], tq);
    }
}

// per-block BN finalize into smem
__device__ __forceinline__ void bn_smem(float* s_scale, float* s_shift, int FI, int soff,
                                        const float* gam, const float* bet) {
    int t = threadIdx.x;
    float sc = 0.f, sh = 0.f;
    if (t < FI) {
        float m = g_stats[soff + t] * (1.0f / N_NODES);
        float v = g_stats[soff + 256 + t] * (1.0f / N_NODES) - m * m;
        float a = __ldg(&gam[t]) * rsqrtf(v + BN_EPS);
        sc = a;
        sh = __ldg(&bet[t]) - m * a;
    }
    s_scale[t] = sc;
    s_shift[t] = sh;
    __syncthreads();
}

// ---------------- layer-1 gather (external fp32 x, FI=7 -> padded 8) ---------
__global__ void __launch_bounds__(256) k_gather1(const float* __restrict__ x,
                                                 const float* __restrict__ gam,
                                                 const float* __restrict__ bet) {
    const int FI = 7, FIP = 8, LPN = 8;
    __shared__ float s_scale[256], s_shift[256];
    bn_smem(s_scale, s_shift, FI, 0, gam, bet);

    int gid = blockIdx.x * blockDim.x + threadIdx.x;
    int node = gid / LPN;
    int lane = gid % LPN;
    if (node >= N_NODES) return;
    int beg = __ldg(&g_off[node]);
    int end = beg + __ldg(&g_deg[node]);
    float dd = __ldg(&g_dinv[node]);
    float acc = 0.f, sums = 0.f;
    int e = beg;
    for (; e + 1 < end; e += 2) {
        int s0 = __ldg(&g_srcarr[e]);
        int s1 = __ldg(&g_srcarr[e + 1]);
        float w0 = __ldg(&g_dinv[s0]);
        float w1 = __ldg(&g_dinv[s1]);
        sums += w0 + w1;
        if (lane < FI) {
            float v0 = __ldg(&x[(size_t)s0 * FI + lane]);
            float v1 = __ldg(&x[(size_t)s1 * FI + lane]);
            acc += w0 * v0 + w1 * v1;
        }
    }
    if (e < end) {
        int s = __ldg(&g_srcarr[e]);
        float wn = __ldg(&g_dinv[s]);
        sums += wn;
        if (lane < FI) acc += wn * __ldg(&x[(size_t)s * FI + lane]);
    }
    float r = s_scale[lane] * (dd * acc) + s_shift[lane] * (dd * sums);
    g_hA[(size_t)node * FIP + lane] = __float2half_rn(r);
}

// ---------------- fp16 gather: LPN lanes/node, 8 halves (uint4) per lane -----
template <int LPN, bool SRC_B>
__global__ void __launch_bounds__(256) k_gatherh(const float* __restrict__ gam,
                                                 const float* __restrict__ bet,
                                                 int FI, int soff) {
    __shared__ float s_scale[256], s_shift[256];
    bn_smem(s_scale, s_shift, FI, soff, gam, bet);

    int gid = blockIdx.x * blockDim.x + threadIdx.x;
    int node = gid / LPN;
    int lane = gid - node * LPN;
    if (node >= N_NODES) return;
    int beg = __ldg(&g_off[node]);
    int end = beg + __ldg(&g_deg[node]);
    float dd = __ldg(&g_dinv[node]);
    const uint4* in8 = (const uint4*)(SRC_B ? g_hB : g_hA);
    uint4* out8 = (uint4*)(SRC_B ? g_hA : g_hB);
    float acc[8];
    #pragma unroll
    for (int q = 0; q < 8; q++) acc[q] = 0.f;
    float sums = 0.f;
    int e = beg;
    for (; e + 1 < end; e += 2) {
        int s0 = __ldg(&g_srcarr[e]);
        int s1 = __ldg(&g_srcarr[e + 1]);
        float w0 = __ldg(&g_dinv[s0]);
        float w1 = __ldg(&g_dinv[s1]);
        sums += w0 + w1;
        uint4 va = __ldg(&in8[(size_t)s0 * LPN + lane]);
        uint4 vb = __ldg(&in8[(size_t)s1 * LPN + lane]);
        float2 a0 = __half22float2(*(__half2*)&va.x);
        float2 a1 = __half22float2(*(__half2*)&va.y);
        float2 a2 = __half22float2(*(__half2*)&va.z);
        float2 a3 = __half22float2(*(__half2*)&va.w);
        float2 b0 = __half22float2(*(__half2*)&vb.x);
        float2 b1 = __half22float2(*(__half2*)&vb.y);
        float2 b2 = __half22float2(*(__half2*)&vb.z);
        float2 b3 = __half22float2(*(__half2*)&vb.w);
        acc[0] += w0 * a0.x + w1 * b0.x; acc[1] += w0 * a0.y + w1 * b0.y;
        acc[2] += w0 * a1.x + w1 * b1.x; acc[3] += w0 * a1.y + w1 * b1.y;
        acc[4] += w0 * a2.x + w1 * b2.x; acc[5] += w0 * a2.y + w1 * b2.y;
        acc[6] += w0 * a3.x + w1 * b3.x; acc[7] += w0 * a3.y + w1 * b3.y;
    }
    if (e < end) {
        int s = __ldg(&g_srcarr[e]);
        float wn = __ldg(&g_dinv[s]);
        sums += wn;
        uint4 v = __ldg(&in8[(size_t)s * LPN + lane]);
        float2 f0 = __half22float2(*(__half2*)&v.x);
        float2 f1 = __half22float2(*(__half2*)&v.y);
        float2 f2 = __half22float2(*(__half2*)&v.z);
        float2 f3 = __half22float2(*(__half2*)&v.w);
        acc[0] += wn * f0.x; acc[1] += wn * f0.y;
        acc[2] += wn * f1.x; acc[3] += wn * f1.y;
        acc[4] += wn * f2.x; acc[5] += wn * f2.y;
        acc[6] += wn * f3.x; acc[7] += wn * f3.y;
    }
    float dsums = dd * sums;
    int c = lane * 8;
    __half2 h[4];
    #pragma unroll
    for (int q = 0; q < 4; q++) {
        float v0 = s_scale[c + 2 * q]     * (dd * acc[2 * q])     + s_shift[c + 2 * q]     * dsums;
        float v1 = s_scale[c + 2 * q + 1] * (dd * acc[2 * q + 1]) + s_shift[c + 2 * q + 1] * dsums;
        h[q] = __floats2half2_rn(v0, v1);
    }
    uint4 o;
    o.x = *(uint32_t*)&h[0]; o.y = *(uint32_t*)&h[1];
    o.z = *(uint32_t*)&h[2]; o.w = *(uint32_t*)&h[3];
    out8[(size_t)node * LPN + lane] = o;
}

// ---------------- fp16 mma GEMM: out = relu(in @ W + bias) -------------------
template <int FIP, int KPAD, int FO, int FOP, int NJ, bool STATS, bool SRC_A>
__global__ void __launch_bounds__(256) k_gemm_h(int woff, int soff,
                                                const float* __restrict__ bias) {
    const int SA = KPAD + 8;
    __shared__ __align__(16) __half Asm[64 * SA];
    __shared__ __align__(16) __half Wsm[64 * SA];
    __shared__ float  sred[64];
    __shared__ float  sqred[64];

    int tid = threadIdx.x;
    int wid = tid >> 5, lane = tid & 31;
    int grp = lane >> 2, tg = lane & 3;
    int mwarp = (wid & 1) * 32;
    int nwarp = (wid >> 1) * 16;
    int n0 = blockIdx.x * 64;
    const __half* inb = SRC_A ? g_hA : g_hB;
    __half* outb = SRC_A ? g_hB : g_hA;

    // stage A once
    {
        const int VR = KPAD / 8;
        const uint4* src = (const uint4*)inb;
        for (int idx = tid; idx < 64 * VR; idx += 256) {
            int r = idx / VR, q = idx - r * VR;
            uint4 v = make_uint4(0, 0, 0, 0);
            if (n0 + r < N_NODES && q < FIP / 8)
                v = __ldg(&src[(size_t)(n0 + r) * (FIP / 8) + q]);
            *(uint4*)&Asm[r * SA + q * 8] = v;
        }
    }

    for (int jc = 0; jc < NJ; jc++) {
        int j0 = jc * 64;
        __syncthreads();
        {
            const uint4* wsrc = (const uint4*)(g_Wt + woff + (size_t)jc * 64 * SA);
            uint4* wdst = (uint4*)Wsm;
            #pragma unroll 4
            for (int i = tid; i < 64 * SA / 8; i += 256) wdst[i] = __ldg(&wsrc[i]);
        }
        if (STATS && tid < 64) { sred[tid] = 0.f; sqred[tid] = 0.f; }
        __syncthreads();

        float c[2][2][4];
        #pragma unroll
        for (int mi = 0; mi < 2; mi++)
            #pragma unroll
            for (int ni = 0; ni < 2; ni++)
                #pragma unroll
                for (int q = 0; q < 4; q++) c[mi][ni][q] = 0.f;

        const int NS = KPAD / 16;
        #pragma unroll
        for (int ks = 0; ks < NS; ks++) {
            int kb = ks * 16;
            uint32_t a[2][4];
            #pragma unroll
            for (int mi = 0; mi < 2; mi++) {
                int row = mwarp + mi * 16 + grp;
                const __half* ap = &Asm[row * SA + kb + 2 * tg];
                a[mi][0] = *(const uint32_t*)ap;
                a[mi][1] = *(const uint32_t*)(ap + 8 * SA);
                a[mi][2] = *(const uint32_t*)(ap + 8);
                a[mi][3] = *(const uint32_t*)(ap + 8 * SA + 8);
            }
            uint32_t b[2][2];
            #pragma unroll
            for (int ni = 0; ni < 2; ni++) {
                int nn = nwarp + ni * 8 + grp;
                const __half* bp = &Wsm[nn * SA + kb + 2 * tg];
                b[ni][0] = *(const uint32_t*)bp;
                b[ni][1] = *(const uint32_t*)(bp + 8);
            }
            #pragma unroll
            for (int mi = 0; mi < 2; mi++)
                #pragma unroll
                for (int ni = 0; ni < 2; ni++) {
                    asm volatile(
                        "mma.sync.aligned.m16n8k16.row.col.f32.f16.f16.f32 "
                        "{%0,%1,%2,%3}, {%4,%5,%6,%7}, {%8,%9}, {%0,%1,%2,%3};"
                        : "+f"(c[mi][ni][0]), "+f"(c[mi][ni][1]),
                          "+f"(c[mi][ni][2]), "+f"(c[mi][ni][3])
                        : "r"(a[mi][0]), "r"(a[mi][1]), "r"(a[mi][2]), "r"(a[mi][3]),
                          "r"(b[ni][0]), "r"(b[ni][1]));
                }
        }

        #pragma unroll
        for (int mi = 0; mi < 2; mi++) {
            int r0 = n0 + mwarp + mi * 16 + grp;
            int r1 = r0 + 8;
            #pragma unroll
            for (int ni = 0; ni < 2; ni++) {
                int jb = j0 + nwarp + ni * 8 + 2 * tg;
                if (jb >= FO) continue;
                float bj0 = __ldg(&bias[jb]);
                float bj1 = (jb + 1 < FO) ? __ldg(&bias[jb + 1]) : 0.f;
                float v00 = c[mi][ni][0] + bj0; v00 = v00 > 0.f ? v00 : 0.f;
                float v01 = c[mi][ni][1] + bj1; v01 = v01 > 0.f ? v01 : 0.f;
                float v10 = c[mi][ni][2] + bj0; v10 = v10 > 0.f ? v10 : 0.f;
                float v11 = c[mi][ni][3] + bj1; v11 = v11 > 0.f ? v11 : 0.f;
                if (jb + 1 >= FO) { v01 = 0.f; v11 = 0.f; }
                bool ok0 = (r0 < N_NODES), ok1 = (r1 < N_NODES);
                __half2 p0 = __floats2half2_rn(v00, v01);
                __half2 p1 = __floats2half2_rn(v10, v11);
                if (ok0) *(uint32_t*)&outb[(size_t)r0 * FOP + jb] = *(uint32_t*)&p0;
                if (ok1) *(uint32_t*)&outb[(size_t)r1 * FOP + jb] = *(uint32_t*)&p1;
                if (STATS) {
                    float s0 = (ok0 ? v00 : 0.f) + (ok1 ? v10 : 0.f);
                    float q0 = (ok0 ? v00 * v00 : 0.f) + (ok1 ? v10 * v10 : 0.f);
                    float s1 = (ok0 ? v01 : 0.f) + (ok1 ? v11 : 0.f);
                    float q1 = (ok0 ? v01 * v01 : 0.f) + (ok1 ? v11 * v11 : 0.f);
                    int cb = nwarp + ni * 8 + 2 * tg;
                    atomicAdd(&sred[cb], s0);
                    atomicAdd(&sqred[cb], q0);
                    atomicAdd(&sred[cb + 1], s1);
                    atomicAdd(&sqred[cb + 1], q1);
                }
            }
        }
        if (STATS) {
            __syncthreads();
            if (tid < 64) {
                int j = j0 + tid;
                if (j < FO) {
                    atomicAdd(&g_stats[soff + j], sred[tid]);
                    atomicAdd(&g_stats[soff + 256 + j], sqred[tid]);
                }
            }
        }
    }
}

// ---------------- pool partial sums: grid (N_GRAPHS, 4) ----------------------
__global__ void __launch_bounds__(256) k_poolpart() {
    const int FO = 199, FOP = 200;
    int g = blockIdx.x;
    int slice = blockIdx.y;
    int s = g_gstart[g], e = g_gstart[g + 1];
    int cnt = e - s;
    if (cnt <= 0) return;
    int per = (cnt + 3) / 4;
    int rs = s + slice * per;
    int re = rs + per;
    if (re > e) re = e;
    if (rs >= re) return;
    int f = threadIdx.x;
    if (f < FO) {
        float a0 = 0.f, a1 = 0.f;
        int n = rs;
        for (; n + 1 < re; n += 2) {
            a0 += __half2float(__ldg(&g_hB[(size_t)n * FOP + f]));
            a1 += __half2float(__ldg(&g_hB[(size_t)(n + 1) * FOP + f]));
        }
        if (n < re) a0 += __half2float(__ldg(&g_hB[(size_t)n * FOP + f]));
        atomicAdd(&g_pooled[g * FOP + f], a0 + a1);
    }
}

// ---------------- MLP head ----------------------------------------------------
__global__ void __launch_bounds__(256) k_mlp(const float* __restrict__ Wl1,
                                             const float* __restrict__ bl1,
                                             const float* __restrict__ Wl2,
                                             const float* __restrict__ bl2,
                                             float* __restrict__ out) {
    const int FO = 199, FOP = 200;
    __shared__ float pooled[FO];
    __shared__ float t1[49];
    int g = blockIdx.x;
    int f = threadIdx.x;
    if (f < FO) {
        int cnt = g_gstart[g + 1] - g_gstart[g];
        pooled[f] = g_pooled[g * FOP + f] / (float)(cnt > 0 ? cnt : 1);
    }
    __syncthreads();
    if (f < 49) {
        float a = bl1[f];
        for (int k = 0; k < FO; k++) a += pooled[k] * Wl1[k * 49 + f];
        t1[f] = a;
    }
    __syncthreads();
    if (f < 2) {
        float a = bl2[f];
        for (int k = 0; k < 49; k++) a += t1[k] * Wl2[k * 2 + f];
        out[g * 2 + f] = a;
    }
}

// ---------------- launch ----------------
extern "C" void kernel_launch(void* const* d_in, const int* in_sizes, int n_in,
                              void* d_out, int out_size) {
    const float* x     = (const float*)d_in[0];
    const void*  ei    = d_in[1];
    const void*  batch = d_in[2];
    const float* bn0g = (const float*)d_in[3];
    const float* bn0b = (const float*)d_in[4];
    const float* bn1g = (const float*)d_in[5];
    const float* bn1b = (const float*)d_in[6];
    const float* bn2g = (const float*)d_in[7];
    const float* bn2b = (const float*)d_in[8];
    const float* W1  = (const float*)d_in[9];
    const float* b1  = (const float*)d_in[10];
    const float* W2  = (const float*)d_in[11];
    const float* b2  = (const float*)d_in[12];
    const float* W3  = (const float*)d_in[13];
    const float* b3  = (const float*)d_in[14];
    const float* Wl1 = (const float*)d_in[15];
    const float* bl1 = (const float*)d_in[16];
    const float* Wl2 = (const float*)d_in[17];
    const float* bl2 = (const float*)d_in[18];
    float* out = (float*)d_out;

    const int NB_N = (N_NODES + 255) / 256;
    const int NB_E = (N_EDGES + 255) / 256;

    // graph preprocessing
    k_init<<<NB_N, 256>>>((const int*)ei);
    k_deg_edges<<<NB_E, 256>>>(ei);
    k_assign<<<NB_N, 256>>>(batch);
    k_fill<<<NB_E, 256>>>(ei);

    // pre-convert weights (single launch)
    k_wprep_all<<<9, 256>>>(W1, W2, W3);

    dim3 sblk(32, 8);
    const int NB_G8  = ((N_NODES * 8)  + 255) / 256;
    const int NB_G9  = ((N_NODES * 9)  + 255) / 256;
    const int NB_G17 = ((N_NODES * 17) + 255) / 256;
    const int GX64 = N_PAD / 64;

    // ---- layer 1: stats buf0 -> gather1(BN0) -> gemm (stats -> buf1)
    k_stats_x<<<dim3(1, 64), sblk>>>(x, 7);
    k_gather1<<<NB_G8, 256>>>(x, bn0g, bn0b);
    k_gemm_h<8, 16, 71, 72, 2, true, true><<<GX64, 256>>>(0, 512, b1);

    // ---- layer 2: gatherh(BN1 from buf1) hB->hA -> gemm (stats -> buf2)
    k_gatherh<9, true><<<NB_G9, 256>>>(bn1g, bn1b, 71, 512);
    k_gemm_h<72, 80, 135, 136, 3, true, true><<<GX64, 256>>>(3072, 1024, b2);

    // ---- layer 3: gatherh(BN2 from buf2) hB->hA -> gemm (no stats)
    k_gatherh<17, true><<<NB_G17, 256>>>(bn2g, bn2b, 135, 1024);
    k_gemm_h<136, 144, 199, 200, 4, false, true><<<GX64, 256>>>(19968, 0, b3);

    // ---- pool + head
    k_poolpart<<<dim3(N_GRAPHS, 4), 256>>>();
    k_mlp<<<N_GRAPHS, 256>>>(Wl1, bl1, Wl2, bl2, out);
}

// round 17
// speedup vs baseline: 1.1964x; 1.0740x over previous
#include <cuda_runtime.h>
#include <cuda_fp16.h>
#include <math.h>
#include <stdint.h>

#define N_NODES 100000
#define N_PAD   100096   // multiple of 128
#define N_EDGES 1600000
#define N_TOT   1700000
#define N_GRAPHS 256
#define BN_EPS 1e-5f

// ---------------- scratch (device globals; no runtime allocation) -------------
__device__ int    g_idx64;
__device__ int    g_ctr;
__device__ int    g_deg[N_NODES];
__device__ float  g_dinv[N_NODES];
__device__ int    g_off[N_NODES];
__device__ int    g_cursor[N_NODES];
__device__ int    g_srcarr[N_TOT];
__device__ __half g_hA[(size_t)N_PAD * 200];
__device__ __half g_hB[(size_t)N_PAD * 200];
__device__ float  g_stats[3 * 512];   // per-layer: [soff+0..255]=sum, [soff+256..511]=sumsq
__device__ float  g_pooled[N_GRAPHS * 200];
__device__ int    g_gstart[N_GRAPHS + 1];
// pre-converted fp16 weights, transposed [n][k], per-chunk stride SA=KPAD+8
__device__ __align__(16) __half g_Wt[58880];

__device__ __forceinline__ int idx_at(const void* p, long i, int is64) {
    if (is64) return (int)((const long long*)p)[i];
    return ((const int*)p)[i];
}
// two consecutive indices at even position i (16B/8B aligned)
__device__ __forceinline__ int2 idx2_at(const void* p, long i, int is64) {
    if (is64) {
        longlong2 v = __ldg((const longlong2*)((const long long*)p + i));
        return make_int2((int)v.x, (int)v.y);
    }
    return __ldg((const int2*)((const int*)p + i));
}

// ---------------- init ----------------
__global__ void __launch_bounds__(256) k_init(const int* __restrict__ ei32) {
    int n = blockIdx.x * blockDim.x + threadIdx.x;
    if (n < N_NODES) g_deg[n] = 1;
    if (n < 3 * 512) g_stats[n] = 0.0f;
    if (n < N_GRAPHS * 200) g_pooled[n] = 0.0f;
    if (n == 0) {
        g_ctr = 0;
        int any = 0;
        for (int k = 0; k < 64; k++)
            if (ei32[2 * k + 1] != 0) { any = 1; break; }
        g_idx64 = !any;
    }
}

// 2 edges per thread (vector index loads)
__global__ void __launch_bounds__(256) k_deg_edges(const void* __restrict__ ei) {
    long e = (long)(blockIdx.x * blockDim.x + threadIdx.x) * 2;
    if (e >= N_EDGES) return;
    int is64 = g_idx64;
    int2 d = idx2_at(ei, (long)N_EDGES + e, is64);
    if ((unsigned)d.x < N_NODES) atomicAdd(&g_deg[d.x], 1);
    if ((unsigned)d.y < N_NODES) atomicAdd(&g_deg[d.y], 1);
}

// single-pass offset assignment: block-local scan + one atomicAdd per block.
// CSR regions are contiguous per node but NOT node-ordered (gathers use off+deg).
__global__ void __launch_bounds__(256) k_assign(const void* __restrict__ batch) {
    __shared__ int sh[256];
    __shared__ int s_base;
    int t = threadIdx.x;
    int n = blockIdx.x * 256 + t;
    int dg = 0;
    float di = 0.f;
    if (n < N_NODES) {
        dg = g_deg[n];
        di = rsqrtf((float)dg);
        g_dinv[n] = di;
    }
    sh[t] = dg;
    __syncthreads();
    for (int o = 1; o < 256; o <<= 1) {
        int v = (t >= o) ? sh[t - o] : 0;
        __syncthreads();
        sh[t] += v;
        __syncthreads();
    }
    if (t == 255) s_base = atomicAdd(&g_ctr, sh[255]);
    __syncthreads();
    if (n < N_NODES) {
        int o = s_base + sh[t] - dg;
        g_off[n] = o;
        g_srcarr[o] = n;     // self loop
        g_cursor[n] = o + 1;
        int is64 = g_idx64;
        int b1 = idx_at(batch, n, is64);
        if (b1 >= 0 && b1 < N_GRAPHS) {
            int b0 = (n == 0) ? -1 : idx_at(batch, n - 1, is64);
            for (int g = b0 + 1; g <= b1; g++) g_gstart[g] = n;
            if (n == N_NODES - 1)
                for (int g = b1 + 1; g <= N_GRAPHS; g++) g_gstart[g] = N_NODES;
        }
    }
}

// fill: indices only, 2 edges per thread
__global__ void __launch_bounds__(256) k_fill(const void* __restrict__ ei) {
    long e = (long)(blockIdx.x * blockDim.x + threadIdx.x) * 2;
    if (e >= N_EDGES) return;
    int is64 = g_idx64;
    int2 s = idx2_at(ei, e, is64);
    int2 d = idx2_at(ei, (long)N_EDGES + e, is64);
    if ((unsigned)s.x < N_NODES && (unsigned)d.x < N_NODES) {
        int pos = atomicAdd(&g_cursor[d.x], 1);
        if ((unsigned)pos < N_TOT) g_srcarr[pos] = s.x;
    }
    if ((unsigned)s.y < N_NODES && (unsigned)d.y < N_NODES) {
        int pos = atomicAdd(&g_cursor[d.y], 1);
        if ((unsigned)pos < N_TOT) g_srcarr[pos] = s.y;
    }
}

// ---------------- W pre-conversion (all 3 layers in one launch, 9 blocks) ----
__global__ void __launch_bounds__(256) k_wprep_all(const float* __restrict__ W1,
                                                   const float* __restrict__ W2,
                                                   const float* __restrict__ W3) {
    int b = blockIdx.x;
    const float* W; int FI, KPAD, FO, off, jc;
    if (b < 2)      { W = W1; FI = 7;   KPAD = 16;  FO = 71;  off = 0;     jc = b; }
    else if (b < 5) { W = W2; FI = 71;  KPAD = 80;  FO = 135; off = 3072;  jc = b - 2; }
    else            { W = W3; FI = 135; KPAD = 144; FO = 199; off = 19968; jc = b - 5; }
    int SA = KPAD + 8;
    int j0 = jc * 64;
    __half* dst = g_Wt + off + jc * 64 * SA;
    for (int idx = threadIdx.x; idx < 64 * SA; idx += 256) {
        int nn = idx / SA, k = idx - nn * SA;
        float v = (k < FI && (j0 + nn) < FO) ? __ldg(&W[k * FO + j0 + nn]) : 0.f;
        dst[idx] = __float2half_rn(v);
    }
}

// ---------------- stats over external x (coalesced, 391 blocks) --------------
// block stages 256 rows (1792 floats) into smem, per-thread 7-col partials,
// warp shuffle-reduce, per-block 7 global atomics.
__global__ void __launch_bounds__(256) k_stats_x(const float* __restrict__ x) {
    const int FI = 7;
    __shared__ float st[256 * FI];
    __shared__ float wsum[8][FI];
    __shared__ float wsq[8][FI];
    int tid = threadIdx.x;
    int wid = tid >> 5, lane = tid & 31;
    long base = (long)blockIdx.x * 256 * FI;
    #pragma unroll
    for (int k = 0; k < FI; k++) {
        long gi = base + tid + k * 256;
        st[tid + k * 256] = (gi < (long)N_NODES * FI) ? __ldg(&x[gi]) : 0.f;
    }
    __syncthreads();
    float s[FI], q[FI];
    #pragma unroll
    for (int f = 0; f < FI; f++) {
        float v = st[tid * FI + f];
        s[f] = v;
        q[f] = v * v;
    }
    #pragma unroll
    for (int o = 16; o; o >>= 1) {
        #pragma unroll
        for (int f = 0; f < FI; f++) {
            s[f] += __shfl_xor_sync(0xFFFFFFFFu, s[f], o);
            q[f] += __shfl_xor_sync(0xFFFFFFFFu, q[f], o);
        }
    }
    if (lane == 0) {
        #pragma unroll
        for (int f = 0; f < FI; f++) { wsum[wid][f] = s[f]; wsq[wid][f] = q[f]; }
    }
    __syncthreads();
    if (tid < FI) {
        float a = 0.f, b = 0.f;
        #pragma unroll
        for (int w = 0; w < 8; w++) { a += wsum[w][tid]; b += wsq[w][tid]; }
        atomicAdd(&g_stats[tid], a);
        atomicAdd(&g_stats[256 + tid], b);
    }
}

// per-block BN finalize into smem
__device__ __forceinline__ void bn_smem(float* s_scale, float* s_shift, int FI, int soff,
                                        const float* gam, const float* bet) {
    int t = threadIdx.x;
    float sc = 0.f, sh = 0.f;
    if (t < FI) {
        float m = g_stats[soff + t] * (1.0f / N_NODES);
        float v = g_stats[soff + 256 + t] * (1.0f / N_NODES) - m * m;
        float a = __ldg(&gam[t]) * rsqrtf(v + BN_EPS);
        sc = a;
        sh = __ldg(&bet[t]) - m * a;
    }
    s_scale[t] = sc;
    s_shift[t] = sh;
    __syncthreads();
}

// ---------------- layer-1 gather (external fp32 x, FI=7 -> padded 8) ---------
__global__ void __launch_bounds__(256) k_gather1(const float* __restrict__ x,
                                                 const float* __restrict__ gam,
                                                 const float* __restrict__ bet) {
    const int FI = 7, FIP = 8, LPN = 8;
    __shared__ float s_scale[256], s_shift[256];
    bn_smem(s_scale, s_shift, FI, 0, gam, bet);

    int gid = blockIdx.x * blockDim.x + threadIdx.x;
    int node = gid / LPN;
    int lane = gid % LPN;
    if (node >= N_NODES) return;
    int beg = __ldg(&g_off[node]);
    int end = beg + __ldg(&g_deg[node]);
    float dd = __ldg(&g_dinv[node]);
    float acc = 0.f, sums = 0.f;
    int e = beg;
    for (; e + 1 < end; e += 2) {
        int s0 = __ldg(&g_srcarr[e]);
        int s1 = __ldg(&g_srcarr[e + 1]);
        float w0 = __ldg(&g_dinv[s0]);
        float w1 = __ldg(&g_dinv[s1]);
        sums += w0 + w1;
        if (lane < FI) {
            float v0 = __ldg(&x[(size_t)s0 * FI + lane]);
            float v1 = __ldg(&x[(size_t)s1 * FI + lane]);
            acc += w0 * v0 + w1 * v1;
        }
    }
    if (e < end) {
        int s = __ldg(&g_srcarr[e]);
        float wn = __ldg(&g_dinv[s]);
        sums += wn;
        if (lane < FI) acc += wn * __ldg(&x[(size_t)s * FI + lane]);
    }
    float r = s_scale[lane] * (dd * acc) + s_shift[lane] * (dd * sums);
    g_hA[(size_t)node * FIP + lane] = __float2half_rn(r);
}

// ---------------- fp16 gather: LPN lanes/node, 8 halves (uint4) per lane -----
template <int LPN, bool SRC_B>
__global__ void __launch_bounds__(256) k_gatherh(const float* __restrict__ gam,
                                                 const float* __restrict__ bet,
                                                 int FI, int soff) {
    __shared__ float s_scale[256], s_shift[256];
    bn_smem(s_scale, s_shift, FI, soff, gam, bet);

    int gid = blockIdx.x * blockDim.x + threadIdx.x;
    int node = gid / LPN;
    int lane = gid - node * LPN;
    if (node >= N_NODES) return;
    int beg = __ldg(&g_off[node]);
    int end = beg + __ldg(&g_deg[node]);
    float dd = __ldg(&g_dinv[node]);
    const uint4* in8 = (const uint4*)(SRC_B ? g_hB : g_hA);
    uint4* out8 = (uint4*)(SRC_B ? g_hA : g_hB);
    float acc[8];
    #pragma unroll
    for (int q = 0; q < 8; q++) acc[q] = 0.f;
    float sums = 0.f;
    int e = beg;
    for (; e + 1 < end; e += 2) {
        int s0 = __ldg(&g_srcarr[e]);
        int s1 = __ldg(&g_srcarr[e + 1]);
        float w0 = __ldg(&g_dinv[s0]);
        float w1 = __ldg(&g_dinv[s1]);
        sums += w0 + w1;
        uint4 va = __ldg(&in8[(size_t)s0 * LPN + lane]);
        uint4 vb = __ldg(&in8[(size_t)s1 * LPN + lane]);
        float2 a0 = __half22float2(*(__half2*)&va.x);
        float2 a1 = __half22float2(*(__half2*)&va.y);
        float2 a2 = __half22float2(*(__half2*)&va.z);
        float2 a3 = __half22float2(*(__half2*)&va.w);
        float2 b0 = __half22float2(*(__half2*)&vb.x);
        float2 b1 = __half22float2(*(__half2*)&vb.y);
        float2 b2 = __half22float2(*(__half2*)&vb.z);
        float2 b3 = __half22float2(*(__half2*)&vb.w);
        acc[0] += w0 * a0.x + w1 * b0.x; acc[1] += w0 * a0.y + w1 * b0.y;
        acc[2] += w0 * a1.x + w1 * b1.x; acc[3] += w0 * a1.y + w1 * b1.y;
        acc[4] += w0 * a2.x + w1 * b2.x; acc[5] += w0 * a2.y + w1 * b2.y;
        acc[6] += w0 * a3.x + w1 * b3.x; acc[7] += w0 * a3.y + w1 * b3.y;
    }
    if (e < end) {
        int s = __ldg(&g_srcarr[e]);
        float wn = __ldg(&g_dinv[s]);
        sums += wn;
        uint4 v = __ldg(&in8[(size_t)s * LPN + lane]);
        float2 f0 = __half22float2(*(__half2*)&v.x);
        float2 f1 = __half22float2(*(__half2*)&v.y);
        float2 f2 = __half22float2(*(__half2*)&v.z);
        float2 f3 = __half22float2(*(__half2*)&v.w);
        acc[0] += wn * f0.x; acc[1] += wn * f0.y;
        acc[2] += wn * f1.x; acc[3] += wn * f1.y;
        acc[4] += wn * f2.x; acc[5] += wn * f2.y;
        acc[6] += wn * f3.x; acc[7] += wn * f3.y;
    }
    float dsums = dd * sums;
    int c = lane * 8;
    __half2 h[4];
    #pragma unroll
    for (int q = 0; q < 4; q++) {
        float v0 = s_scale[c + 2 * q]     * (dd * acc[2 * q])     + s_shift[c + 2 * q]     * dsums;
        float v1 = s_scale[c + 2 * q + 1] * (dd * acc[2 * q + 1]) + s_shift[c + 2 * q + 1] * dsums;
        h[q] = __floats2half2_rn(v0, v1);
    }
    uint4 o;
    o.x = *(uint32_t*)&h[0]; o.y = *(uint32_t*)&h[1];
    o.z = *(uint32_t*)&h[2]; o.w = *(uint32_t*)&h[3];
    out8[(size_t)node * LPN + lane] = o;
}

// ---------------- fp16 mma GEMM: out = relu(in @ W + bias) -------------------
template <int FIP, int KPAD, int FO, int FOP, int NJ, bool STATS, bool SRC_A>
__global__ void __launch_bounds__(256) k_gemm_h(int woff, int soff,
                                                const float* __restrict__ bias) {
    const int SA = KPAD + 8;
    __shared__ __align__(16) __half Asm[64 * SA];
    __shared__ __align__(16) __half Wsm[64 * SA];
    __shared__ float  sred[64];
    __shared__ float  sqred[64];

    int tid = threadIdx.x;
    int wid = tid >> 5, lane = tid & 31;
    int grp = lane >> 2, tg = lane & 3;
    int mwarp = (wid & 1) * 32;
    int nwarp = (wid >> 1) * 16;
    int n0 = blockIdx.x * 64;
    const __half* inb = SRC_A ? g_hA : g_hB;
    __half* outb = SRC_A ? g_hB : g_hA;

    // stage A once
    {
        const int VR = KPAD / 8;
        const uint4* src = (const uint4*)inb;
        for (int idx = tid; idx < 64 * VR; idx += 256) {
            int r = idx / VR, q = idx - r * VR;
            uint4 v = make_uint4(0, 0, 0, 0);
            if (n0 + r < N_NODES && q < FIP / 8)
                v = __ldg(&src[(size_t)(n0 + r) * (FIP / 8) + q]);
            *(uint4*)&Asm[r * SA + q * 8] = v;
        }
    }

    for (int jc = 0; jc < NJ; jc++) {
        int j0 = jc * 64;
        __syncthreads();
        {
            const uint4* wsrc = (const uint4*)(g_Wt + woff + (size_t)jc * 64 * SA);
            uint4* wdst = (uint4*)Wsm;
            #pragma unroll 4
            for (int i = tid; i < 64 * SA / 8; i += 256) wdst[i] = __ldg(&wsrc[i]);
        }
        if (STATS && tid < 64) { sred[tid] = 0.f; sqred[tid] = 0.f; }
        __syncthreads();

        float c[2][2][4];
        #pragma unroll
        for (int mi = 0; mi < 2; mi++)
            #pragma unroll
            for (int ni = 0; ni < 2; ni++)
                #pragma unroll
                for (int q = 0; q < 4; q++) c[mi][ni][q] = 0.f;

        const int NS = KPAD / 16;
        #pragma unroll
        for (int ks = 0; ks < NS; ks++) {
            int kb = ks * 16;
            uint32_t a[2][4];
            #pragma unroll
            for (int mi = 0; mi < 2; mi++) {
                int row = mwarp + mi * 16 + grp;
                const __half* ap = &Asm[row * SA + kb + 2 * tg];
                a[mi][0] = *(const uint32_t*)ap;
                a[mi][1] = *(const uint32_t*)(ap + 8 * SA);
                a[mi][2] = *(const uint32_t*)(ap + 8);
                a[mi][3] = *(const uint32_t*)(ap + 8 * SA + 8);
            }
            uint32_t b[2][2];
            #pragma unroll
            for (int ni = 0; ni < 2; ni++) {
                int nn = nwarp + ni * 8 + grp;
                const __half* bp = &Wsm[nn * SA + kb + 2 * tg];
                b[ni][0] = *(const uint32_t*)bp;
                b[ni][1] = *(const uint32_t*)(bp + 8);
            }
            #pragma unroll
            for (int mi = 0; mi < 2; mi++)
                #pragma unroll
                for (int ni = 0; ni < 2; ni++) {
                    asm volatile(
                        "mma.sync.aligned.m16n8k16.row.col.f32.f16.f16.f32 "
                        "{%0,%1,%2,%3}, {%4,%5,%6,%7}, {%8,%9}, {%0,%1,%2,%3};"
                        : "+f"(c[mi][ni][0]), "+f"(c[mi][ni][1]),
                          "+f"(c[mi][ni][2]), "+f"(c[mi][ni][3])
                        : "r"(a[mi][0]), "r"(a[mi][1]), "r"(a[mi][2]), "r"(a[mi][3]),
                          "r"(b[ni][0]), "r"(b[ni][1]));
                }
        }

        #pragma unroll
        for (int mi = 0; mi < 2; mi++) {
            int r0 = n0 + mwarp + mi * 16 + grp;
            int r1 = r0 + 8;
            #pragma unroll
            for (int ni = 0; ni < 2; ni++) {
                int jb = j0 + nwarp + ni * 8 + 2 * tg;
                if (jb >= FO) continue;
                float bj0 = __ldg(&bias[jb]);
                float bj1 = (jb + 1 < FO) ? __ldg(&bias[jb + 1]) : 0.f;
                float v00 = c[mi][ni][0] + bj0; v00 = v00 > 0.f ? v00 : 0.f;
                float v01 = c[mi][ni][1] + bj1; v01 = v01 > 0.f ? v01 : 0.f;
                float v10 = c[mi][ni][2] + bj0; v10 = v10 > 0.f ? v10 : 0.f;
                float v11 = c[mi][ni][3] + bj1; v11 = v11 > 0.f ? v11 : 0.f;
                if (jb + 1 >= FO) { v01 = 0.f; v11 = 0.f; }
                bool ok0 = (r0 < N_NODES), ok1 = (r1 < N_NODES);
                __half2 p0 = __floats2half2_rn(v00, v01);
                __half2 p1 = __floats2half2_rn(v10, v11);
                if (ok0) *(uint32_t*)&outb[(size_t)r0 * FOP + jb] = *(uint32_t*)&p0;
                if (ok1) *(uint32_t*)&outb[(size_t)r1 * FOP + jb] = *(uint32_t*)&p1;
                if (STATS) {
                    float s0 = (ok0 ? v00 : 0.f) + (ok1 ? v10 : 0.f);
                    float q0 = (ok0 ? v00 * v00 : 0.f) + (ok1 ? v10 * v10 : 0.f);
                    float s1 = (ok0 ? v01 : 0.f) + (ok1 ? v11 : 0.f);
                    float q1 = (ok0 ? v01 * v01 : 0.f) + (ok1 ? v11 * v11 : 0.f);
                    int cb = nwarp + ni * 8 + 2 * tg;
                    atomicAdd(&sred[cb], s0);
                    atomicAdd(&sqred[cb], q0);
                    atomicAdd(&sred[cb + 1], s1);
                    atomicAdd(&sqred[cb + 1], q1);
                }
            }
        }
        if (STATS) {
            __syncthreads();
            if (tid < 64) {
                int j = j0 + tid;
                if (j < FO) {
                    atomicAdd(&g_stats[soff + j], sred[tid]);
                    atomicAdd(&g_stats[soff + 256 + j], sqred[tid]);
                }
            }
        }
    }
}

// ---------------- pool partial sums: grid (N_GRAPHS, 4) ----------------------
__global__ void __launch_bounds__(256) k_poolpart() {
    const int FO = 199, FOP = 200;
    int g = blockIdx.x;
    int slice = blockIdx.y;
    int s = g_gstart[g], e = g_gstart[g + 1];
    int cnt = e - s;
    if (cnt <= 0) return;
    int per = (cnt + 3) / 4;
    int rs = s + slice * per;
    int re = rs + per;
    if (re > e) re = e;
    if (rs >= re) return;
    int f = threadIdx.x;
    if (f < FO) {
        float a0 = 0.f, a1 = 0.f;
        int n = rs;
        for (; n + 1 < re; n += 2) {
            a0 += __half2float(__ldg(&g_hB[(size_t)n * FOP + f]));
            a1 += __half2float(__ldg(&g_hB[(size_t)(n + 1) * FOP + f]));
        }
        if (n < re) a0 += __half2float(__ldg(&g_hB[(size_t)n * FOP + f]));
        atomicAdd(&g_pooled[g * FOP + f], a0 + a1);
    }
}

// ---------------- MLP head ----------------------------------------------------
__global__ void __launch_bounds__(256) k_mlp(const float* __restrict__ Wl1,
                                             const float* __restrict__ bl1,
                                             const float* __restrict__ Wl2,
                                             const float* __restrict__ bl2,
                                             float* __restrict__ out) {
    const int FO = 199, FOP = 200;
    __shared__ float pooled[FO];
    __shared__ float t1[49];
    int g = blockIdx.x;
    int f = threadIdx.x;
    if (f < FO) {
        int cnt = g_gstart[g + 1] - g_gstart[g];
        pooled[f] = g_pooled[g * FOP + f] / (float)(cnt > 0 ? cnt : 1);
    }
    __syncthreads();
    if (f < 49) {
        float a = bl1[f];
        for (int k = 0; k < FO; k++) a += pooled[k] * Wl1[k * 49 + f];
        t1[f] = a;
    }
    __syncthreads();
    if (f < 2) {
        float a = bl2[f];
        for (int k = 0; k < 49; k++) a += t1[k] * Wl2[k * 2 + f];
        out[g * 2 + f] = a;
    }
}

// ---------------- launch ----------------
extern "C" void kernel_launch(void* const* d_in, const int* in_sizes, int n_in,
                              void* d_out, int out_size) {
    const float* x     = (const float*)d_in[0];
    const void*  ei    = d_in[1];
    const void*  batch = d_in[2];
    const float* bn0g = (const float*)d_in[3];
    const float* bn0b = (const float*)d_in[4];
    const float* bn1g = (const float*)d_in[5];
    const float* bn1b = (const float*)d_in[6];
    const float* bn2g = (const float*)d_in[7];
    const float* bn2b = (const float*)d_in[8];
    const float* W1  = (const float*)d_in[9];
    const float* b1  = (const float*)d_in[10];
    const float* W2  = (const float*)d_in[11];
    const float* b2  = (const float*)d_in[12];
    const float* W3  = (const float*)d_in[13];
    const float* b3  = (const float*)d_in[14];
    const float* Wl1 = (const float*)d_in[15];
    const float* bl1 = (const float*)d_in[16];
    const float* Wl2 = (const float*)d_in[17];
    const float* bl2 = (const float*)d_in[18];
    float* out = (float*)d_out;

    const int NB_N  = (N_NODES + 255) / 256;
    const int NB_E2 = ((N_EDGES / 2) + 255) / 256;

    // graph preprocessing
    k_init<<<NB_N, 256>>>((const int*)ei);
    k_deg_edges<<<NB_E2, 256>>>(ei);
    k_assign<<<NB_N, 256>>>(batch);
    k_fill<<<NB_E2, 256>>>(ei);

    // pre-convert weights (single launch)
    k_wprep_all<<<9, 256>>>(W1, W2, W3);

    const int NB_G8  = ((N_NODES * 8)  + 255) / 256;
    const int NB_G9  = ((N_NODES * 9)  + 255) / 256;
    const int NB_G17 = ((N_NODES * 17) + 255) / 256;
    const int GX64 = N_PAD / 64;

    // ---- layer 1: stats buf0 -> gather1(BN0) -> gemm (stats -> buf1)
    k_stats_x<<<NB_N, 256>>>(x);
    k_gather1<<<NB_G8, 256>>>(x, bn0g, bn0b);
    k_gemm_h<8, 16, 71, 72, 2, true, true><<<GX64, 256>>>(0, 512, b1);

    // ---- layer 2: gatherh(BN1 from buf1) hB->hA -> gemm (stats -> buf2)
    k_gatherh<9, true><<<NB_G9, 256>>>(bn1g, bn1b, 71, 512);
    k_gemm_h<72, 80, 135, 136, 3, true, true><<<GX64, 256>>>(3072, 1024, b2);

    // ---- layer 3: gatherh(BN2 from buf2) hB->hA -> gemm (no stats)
    k_gatherh<17, true><<<NB_G17, 256>>>(bn2g, bn2b, 135, 1024);
    k_gemm_h<136, 144, 199, 200, 4, false, true><<<GX64, 256>>>(19968, 0, b3);

    // ---- pool + head
    k_poolpart<<<dim3(N_GRAPHS, 4), 256>>>();
    k_mlp<<<N_GRAPHS, 256>>>(Wl1, bl1, Wl2, bl2, out);
}